// round 3
// baseline (speedup 1.0000x reference)
#include <cuda_runtime.h>
#include <cuda_bf16.h>
#include <math.h>

// Problem constants
#define BB    2
#define SS    2048
#define DD    2048
#define HH    16
#define KVH   4
#define DHD   128
#define WIN   128
#define MTOK  (BB*SS)          // 4096 tokens

// ---------------- scratch (device globals; no allocation allowed) ----------
__device__ float g_q[MTOK * HH * DHD];     // 32 MB
__device__ float g_k[MTOK * KVH * DHD];    // 8 MB
__device__ float g_v[MTOK * KVH * DHD];    // 8 MB
__device__ float g_att[MTOK * HH * DHD];   // 32 MB
__device__ float g_cos[SS * 64];
__device__ float g_sin[SS * 64];

// ---------------- RoPE tables (double precision compute, tiny) -------------
__global__ void rope_tables_kernel() {
    int idx = blockIdx.x * blockDim.x + threadIdx.x;
    if (idx >= SS * 64) return;
    int s = idx >> 6;
    int j = idx & 63;
    // inv_freq[j] = theta^(-2j/128)
    double freq = exp(-((double)(2 * j) / 128.0) * 9.210340371976184); // ln(10000)
    double a = (double)s * freq;
    g_cos[idx] = (float)cos(a);
    g_sin[idx] = (float)sin(a);
}

// ---------------- RoPE apply ------------------------------------------------
// t layout: [MTOK][nheads][128]. Pair (i, i+64), cos_rep[i] = cos(f_{i/2}).
__global__ void rope_apply_kernel(float* __restrict__ t, int nheads) {
    int idx = blockIdx.x * blockDim.x + threadIdx.x;
    int total = MTOK * nheads * 64;
    if (idx >= total) return;
    int i   = idx & 63;
    int h   = (idx >> 6) % nheads;
    int tok = idx / (64 * nheads);
    int pos = tok & (SS - 1);
    float* p = t + ((size_t)tok * nheads + h) * DHD;
    float x0 = p[i];
    float x1 = p[i + 64];
    int j = i >> 1;
    float c0 = g_cos[pos * 64 + j],      s0 = g_sin[pos * 64 + j];
    float c1 = g_cos[pos * 64 + 32 + j], s1 = g_sin[pos * 64 + 32 + j];
    p[i]      = x0 * c0 - x1 * s0;
    p[i + 64] = x1 * c1 + x0 * s1;
}

// ---------------- SGEMM: C[M,N] = A[M,K] * B[N,K]^T (both row-major) --------
#define GBM 128
#define GBN 128
#define GBK 16
#define APAD 132   // padded smem row to cut STS bank conflicts

__global__ __launch_bounds__(256, 2)
void sgemm_nt(const float* __restrict__ A, const float* __restrict__ B,
              float* __restrict__ C, int M, int N, int K) {
    __shared__ float As[GBK][APAD];
    __shared__ float Bs[GBK][APAD];
    const int tid = threadIdx.x;
    const int m0 = blockIdx.y * GBM;
    const int n0 = blockIdx.x * GBN;
    const int tm = tid >> 4;       // 0..15
    const int tn = tid & 15;       // 0..15
    const int lr = tid >> 2;       // 0..63
    const int lk = (tid & 3) * 4;  // 0,4,8,12

    float acc[8][8];
#pragma unroll
    for (int i = 0; i < 8; i++)
#pragma unroll
        for (int j = 0; j < 8; j++) acc[i][j] = 0.f;

    const float* Arow0 = A + (size_t)(m0 + lr) * K + lk;
    const float* Arow1 = A + (size_t)(m0 + lr + 64) * K + lk;
    const float* Brow0 = B + (size_t)(n0 + lr) * K + lk;
    const float* Brow1 = B + (size_t)(n0 + lr + 64) * K + lk;

    for (int k0 = 0; k0 < K; k0 += GBK) {
        float4 a0 = *(const float4*)(Arow0 + k0);
        float4 a1 = *(const float4*)(Arow1 + k0);
        float4 b0 = *(const float4*)(Brow0 + k0);
        float4 b1 = *(const float4*)(Brow1 + k0);
        __syncthreads();
        As[lk + 0][lr] = a0.x; As[lk + 1][lr] = a0.y;
        As[lk + 2][lr] = a0.z; As[lk + 3][lr] = a0.w;
        As[lk + 0][lr + 64] = a1.x; As[lk + 1][lr + 64] = a1.y;
        As[lk + 2][lr + 64] = a1.z; As[lk + 3][lr + 64] = a1.w;
        Bs[lk + 0][lr] = b0.x; Bs[lk + 1][lr] = b0.y;
        Bs[lk + 2][lr] = b0.z; Bs[lk + 3][lr] = b0.w;
        Bs[lk + 0][lr + 64] = b1.x; Bs[lk + 1][lr + 64] = b1.y;
        Bs[lk + 2][lr + 64] = b1.z; Bs[lk + 3][lr + 64] = b1.w;
        __syncthreads();
#pragma unroll
        for (int kk = 0; kk < GBK; kk++) {
            float a[8], b[8];
            *(float4*)&a[0] = *(const float4*)&As[kk][tm * 8];
            *(float4*)&a[4] = *(const float4*)&As[kk][tm * 8 + 4];
            *(float4*)&b[0] = *(const float4*)&Bs[kk][tn * 8];
            *(float4*)&b[4] = *(const float4*)&Bs[kk][tn * 8 + 4];
#pragma unroll
            for (int i = 0; i < 8; i++)
#pragma unroll
                for (int j = 0; j < 8; j++) acc[i][j] += a[i] * b[j];
        }
    }
#pragma unroll
    for (int i = 0; i < 8; i++) {
        float4 v0 = make_float4(acc[i][0], acc[i][1], acc[i][2], acc[i][3]);
        float4 v1 = make_float4(acc[i][4], acc[i][5], acc[i][6], acc[i][7]);
        float* crow = C + (size_t)(m0 + tm * 8 + i) * N + n0 + tn * 8;
        *(float4*)(crow) = v0;
        *(float4*)(crow + 4) = v1;
    }
}

// ---------------- Flash attention (full past + 128 lookahead) ---------------
// BQ=128 queries per block, BK=64 keys per iteration, 256 threads.
// Score phase: 16x16 thread grid, 8 rows x 4 cols each.
// PV phase:    16x16 thread grid, 8 rows x 8 cols each.
#define ABQ 128
#define ABK 64
#define ATT_SMEM_FLOATS (128*128 + 128*64 + 64*128 + 64*128)
#define ATT_SMEM_BYTES  (ATT_SMEM_FLOATS * 4)

__global__ __launch_bounds__(256, 1)
void attn_kernel(const float* __restrict__ Q, const float* __restrict__ Kg,
                 const float* __restrict__ Vg, float* __restrict__ O) {
    extern __shared__ float sm[];
    float* QsT = sm;                // [128 d][128 r]
    float* KsT = QsT + 128 * 128;   // [128 d][64 c]
    float* Vs  = KsT + 128 * 64;    // [64 k][128 d]
    float* PsT = Vs + 64 * 128;     // [64 k][128 r]

    const int tid = threadIdx.x;
    const int q0  = blockIdx.x * ABQ;
    const int h   = blockIdx.y;
    const int b   = blockIdx.z;
    const int kvh = h >> 2;
    const float scale = 0.08838834764831845f;  // 1/sqrt(128)

    // ---- load Q tile (transposed, pre-scaled) ----
    {
        const float* Qb = Q + (((size_t)b * SS + q0) * HH + h) * DHD;
        int r = tid >> 1;
        int dbase = (tid & 1) * 64;
#pragma unroll
        for (int i = 0; i < 16; i++) {
            int d = dbase + i * 4;
            float4 v = *(const float4*)&Qb[(size_t)r * (HH * DHD) + d];
            QsT[(d + 0) * 128 + r] = v.x * scale;
            QsT[(d + 1) * 128 + r] = v.y * scale;
            QsT[(d + 2) * 128 + r] = v.z * scale;
            QsT[(d + 3) * 128 + r] = v.w * scale;
        }
    }

    const int ty = tid >> 4;   // 0..15 -> rows ty*8..+7
    const int tx = tid & 15;   // 0..15 -> score cols tx*4..+3 / out cols tx*8..+7

    float m[8], l[8], acc[8][8];
#pragma unroll
    for (int i = 0; i < 8; i++) {
        m[i] = -1e30f; l[i] = 0.f;
#pragma unroll
        for (int j = 0; j < 8; j++) acc[i][j] = 0.f;
    }

    int kv_end = q0 + ABQ + WIN;          // last allowed key + 1 (rounded to 64)
    if (kv_end > SS) kv_end = SS;

    for (int j0 = 0; j0 < kv_end; j0 += ABK) {
        __syncthreads();  // previous iteration's PV reads done
        // ---- load K (transposed) and V ----
        {
            const float* Kb = Kg + (((size_t)b * SS + j0) * KVH + kvh) * DHD;
            int c = tid >> 2;
            int dbase = (tid & 3) * 32;
#pragma unroll
            for (int i = 0; i < 8; i++) {
                int d = dbase + i * 4;
                float4 v = *(const float4*)&Kb[(size_t)c * (KVH * DHD) + d];
                KsT[(d + 0) * 64 + c] = v.x;
                KsT[(d + 1) * 64 + c] = v.y;
                KsT[(d + 2) * 64 + c] = v.z;
                KsT[(d + 3) * 64 + c] = v.w;
            }
            const float* Vb = Vg + (((size_t)b * SS + j0) * KVH + kvh) * DHD;
            int vr = tid >> 2;
            int vd = (tid & 3) * 32;
#pragma unroll
            for (int i = 0; i < 8; i++) {
                *(float4*)&Vs[vr * 128 + vd + i * 4] =
                    *(const float4*)&Vb[(size_t)vr * (KVH * DHD) + vd + i * 4];
            }
        }
        __syncthreads();

        // ---- scores S = Q K^T : 8x4 per thread ----
        float s[8][4];
#pragma unroll
        for (int i = 0; i < 8; i++)
#pragma unroll
            for (int j = 0; j < 4; j++) s[i][j] = 0.f;

#pragma unroll 4
        for (int d = 0; d < DHD; d++) {
            float a[8], bb[4];
            *(float4*)&a[0] = *(const float4*)&QsT[d * 128 + ty * 8];
            *(float4*)&a[4] = *(const float4*)&QsT[d * 128 + ty * 8 + 4];
            *(float4*)&bb[0] = *(const float4*)&KsT[d * 64 + tx * 4];
#pragma unroll
            for (int i = 0; i < 8; i++)
#pragma unroll
                for (int j = 0; j < 4; j++) s[i][j] += a[i] * bb[j];
        }

        // ---- mask (k <= q + WIN); only the last couple of blocks need it ----
        if (j0 + ABK - 1 > q0 + WIN) {
#pragma unroll
            for (int i = 0; i < 8; i++) {
                int q = q0 + ty * 8 + i;
#pragma unroll
                for (int j = 0; j < 4; j++) {
                    int k = j0 + tx * 4 + j;
                    if (k > q + WIN) s[i][j] = -1e30f;
                }
            }
        }

        // ---- online softmax (row reductions across 16 lanes sharing ty) ----
#pragma unroll
        for (int i = 0; i < 8; i++) {
            float mx = fmaxf(fmaxf(s[i][0], s[i][1]), fmaxf(s[i][2], s[i][3]));
#pragma unroll
            for (int o = 8; o >= 1; o >>= 1)
                mx = fmaxf(mx, __shfl_xor_sync(0xffffffffu, mx, o));
            float mnew = fmaxf(m[i], mx);
            float p0 = __expf(s[i][0] - mnew);
            float p1 = __expf(s[i][1] - mnew);
            float p2 = __expf(s[i][2] - mnew);
            float p3 = __expf(s[i][3] - mnew);
            float ls = p0 + p1 + p2 + p3;
#pragma unroll
            for (int o = 8; o >= 1; o >>= 1)
                ls += __shfl_xor_sync(0xffffffffu, ls, o);
            float alpha = __expf(m[i] - mnew);
            m[i] = mnew;
            l[i] = l[i] * alpha + ls;
#pragma unroll
            for (int j = 0; j < 8; j++) acc[i][j] *= alpha;
            int r = ty * 8 + i;
            PsT[(tx * 4 + 0) * 128 + r] = p0;
            PsT[(tx * 4 + 1) * 128 + r] = p1;
            PsT[(tx * 4 + 2) * 128 + r] = p2;
            PsT[(tx * 4 + 3) * 128 + r] = p3;
        }
        __syncthreads();

        // ---- O += P V : 8x8 per thread ----
#pragma unroll 2
        for (int kk = 0; kk < ABK; kk++) {
            float p[8], v[8];
            *(float4*)&p[0] = *(const float4*)&PsT[kk * 128 + ty * 8];
            *(float4*)&p[4] = *(const float4*)&PsT[kk * 128 + ty * 8 + 4];
            *(float4*)&v[0] = *(const float4*)&Vs[kk * 128 + tx * 8];
            *(float4*)&v[4] = *(const float4*)&Vs[kk * 128 + tx * 8 + 4];
#pragma unroll
            for (int i = 0; i < 8; i++)
#pragma unroll
                for (int j = 0; j < 8; j++) acc[i][j] += p[i] * v[j];
        }
    }

    // ---- epilogue: normalize and store [B,S,H*DH] token-major ----
    float* Ob = O + (((size_t)b * SS + q0) * HH + h) * DHD;
#pragma unroll
    for (int i = 0; i < 8; i++) {
        float inv = 1.0f / l[i];
        int r = ty * 8 + i;
        float4 o0 = make_float4(acc[i][0] * inv, acc[i][1] * inv,
                                acc[i][2] * inv, acc[i][3] * inv);
        float4 o1 = make_float4(acc[i][4] * inv, acc[i][5] * inv,
                                acc[i][6] * inv, acc[i][7] * inv);
        float* orow = Ob + (size_t)r * (HH * DHD) + tx * 8;
        *(float4*)(orow) = o0;
        *(float4*)(orow + 4) = o1;
    }
}

// ---------------- launch ----------------------------------------------------
extern "C" void kernel_launch(void* const* d_in, const int* in_sizes, int n_in,
                              void* d_out, int out_size) {
    const float* x  = (const float*)d_in[0];
    const float* Wq = (const float*)d_in[1];
    const float* Wk = (const float*)d_in[2];
    const float* Wv = (const float*)d_in[3];
    const float* Wo = (const float*)d_in[4];
    float* out = (float*)d_out;

    void *pq, *pk, *pv, *pa;
    cudaGetSymbolAddress(&pq, g_q);
    cudaGetSymbolAddress(&pk, g_k);
    cudaGetSymbolAddress(&pv, g_v);
    cudaGetSymbolAddress(&pa, g_att);
    float* Qb = (float*)pq;
    float* Kb = (float*)pk;
    float* Vb = (float*)pv;
    float* Ab = (float*)pa;

    cudaFuncSetAttribute(attn_kernel,
                         cudaFuncAttributeMaxDynamicSharedMemorySize,
                         ATT_SMEM_BYTES);

    // RoPE tables
    rope_tables_kernel<<<(SS * 64 + 255) / 256, 256>>>();

    // QKV projections: C = x @ W^T
    sgemm_nt<<<dim3((HH * DHD) / GBN, MTOK / GBM), 256>>>(x, Wq, Qb, MTOK, HH * DHD, DD);
    sgemm_nt<<<dim3((KVH * DHD) / GBN, MTOK / GBM), 256>>>(x, Wk, Kb, MTOK, KVH * DHD, DD);
    sgemm_nt<<<dim3((KVH * DHD) / GBN, MTOK / GBM), 256>>>(x, Wv, Vb, MTOK, KVH * DHD, DD);

    // RoPE (in place)
    rope_apply_kernel<<<(MTOK * HH * 64 + 255) / 256, 256>>>(Qb, HH);
    rope_apply_kernel<<<(MTOK * KVH * 64 + 255) / 256, 256>>>(Kb, KVH);

    // Attention
    attn_kernel<<<dim3(SS / ABQ, HH, BB), 256, ATT_SMEM_BYTES>>>(Qb, Kb, Vb, Ab);

    // Output projection: out = att @ Wo^T
    sgemm_nt<<<dim3(DD / GBN, MTOK / GBM), 256>>>(Ab, Wo, out, MTOK, DD, HH * DHD);
}

// round 5
// speedup vs baseline: 1.5373x; 1.5373x over previous
#include <cuda_runtime.h>
#include <cuda_bf16.h>
#include <math.h>
#include <stdint.h>

// Problem constants
#define BB    2
#define SS    2048
#define DD    2048
#define HH    16
#define KVH   4
#define DHD   128
#define WIN   128
#define MTOK  (BB*SS)          // 4096 tokens
#define NQ    (HH*DHD)         // 2048
#define NKV   (KVH*DHD)        // 512

// ---------------- scratch (device globals; no allocation allowed) ----------
__device__ __align__(256) float g_q[MTOK * NQ];      // 32 MB
__device__ __align__(256) float g_k[MTOK * NKV];     // 8 MB
__device__ __align__(256) float g_v[MTOK * NKV];     // 8 MB
__device__ __align__(256) float g_att[MTOK * NQ];    // 32 MB
__device__ float g_cos[SS * 64];
__device__ float g_sin[SS * 64];
// hi/lo bf16 splits
__device__ __align__(256) __nv_bfloat16 g_xhi[MTOK * DD],  g_xlo[MTOK * DD];
__device__ __align__(256) __nv_bfloat16 g_wqhi[NQ * DD],   g_wqlo[NQ * DD];
__device__ __align__(256) __nv_bfloat16 g_wkhi[NKV * DD],  g_wklo[NKV * DD];
__device__ __align__(256) __nv_bfloat16 g_wvhi[NKV * DD],  g_wvlo[NKV * DD];
__device__ __align__(256) __nv_bfloat16 g_wohi[DD * NQ],   g_wolo[DD * NQ];
__device__ __align__(256) __nv_bfloat16 g_ahi[MTOK * NQ],  g_alo[MTOK * NQ];

// ---------------- RoPE tables ----------------------------------------------
__global__ void rope_tables_kernel() {
    int idx = blockIdx.x * blockDim.x + threadIdx.x;
    if (idx >= SS * 64) return;
    int s = idx >> 6;
    int j = idx & 63;
    double freq = exp(-((double)(2 * j) / 128.0) * 9.210340371976184); // ln(10000)
    double a = (double)s * freq;
    g_cos[idx] = (float)cos(a);
    g_sin[idx] = (float)sin(a);
}

// ---------------- RoPE apply ------------------------------------------------
__global__ void rope_apply_kernel(float* __restrict__ t, int nheads) {
    int idx = blockIdx.x * blockDim.x + threadIdx.x;
    int total = MTOK * nheads * 64;
    if (idx >= total) return;
    int i   = idx & 63;
    int h   = (idx >> 6) % nheads;
    int tok = idx / (64 * nheads);
    int pos = tok & (SS - 1);
    float* p = t + ((size_t)tok * nheads + h) * DHD;
    float x0 = p[i];
    float x1 = p[i + 64];
    int j = i >> 1;
    float c0 = g_cos[pos * 64 + j],      s0 = g_sin[pos * 64 + j];
    float c1 = g_cos[pos * 64 + 32 + j], s1 = g_sin[pos * 64 + 32 + j];
    p[i]      = x0 * c0 - x1 * s0;
    p[i + 64] = x1 * c1 + x0 * s1;
}

// ---------------- hi/lo bf16 split ------------------------------------------
__global__ void split_kernel(const float* __restrict__ src,
                             __nv_bfloat16* __restrict__ hi,
                             __nv_bfloat16* __restrict__ lo, int n4) {
    int i = blockIdx.x * blockDim.x + threadIdx.x;
    if (i >= n4) return;
    float4 v = ((const float4*)src)[i];
    __nv_bfloat16 h0 = __float2bfloat16(v.x);
    __nv_bfloat16 h1 = __float2bfloat16(v.y);
    __nv_bfloat16 h2 = __float2bfloat16(v.z);
    __nv_bfloat16 h3 = __float2bfloat16(v.w);
    __nv_bfloat16 l0 = __float2bfloat16(v.x - __bfloat162float(h0));
    __nv_bfloat16 l1 = __float2bfloat16(v.y - __bfloat162float(h1));
    __nv_bfloat16 l2 = __float2bfloat16(v.z - __bfloat162float(h2));
    __nv_bfloat16 l3 = __float2bfloat16(v.w - __bfloat162float(h3));
    __nv_bfloat162* ph = (__nv_bfloat162*)hi;
    __nv_bfloat162* pl = (__nv_bfloat162*)lo;
    ph[2 * i]     = __nv_bfloat162(h0, h1);
    ph[2 * i + 1] = __nv_bfloat162(h2, h3);
    pl[2 * i]     = __nv_bfloat162(l0, l1);
    pl[2 * i + 1] = __nv_bfloat162(l2, l3);
}

// ---------------- PTX helpers (all non-'a' features: sm_80/75 era) ----------
__device__ __forceinline__ uint32_t s2u(const void* p) {
    uint32_t a;
    asm("{ .reg .u64 t; cvta.to.shared.u64 t, %1; cvt.u32.u64 %0, t; }"
        : "=r"(a) : "l"(p));
    return a;
}

#define CP16(saddr, gptr) \
    asm volatile("cp.async.cg.shared.global [%0], [%1], 16;" \
                 :: "r"(saddr), "l"(gptr))
#define CP_COMMIT() asm volatile("cp.async.commit_group;" ::: "memory")
#define CP_WAIT0()  asm volatile("cp.async.wait_group 0;" ::: "memory")
#define CP_WAIT1()  asm volatile("cp.async.wait_group 1;" ::: "memory")

#define LDM_X4(R, addr) \
    asm volatile("ldmatrix.sync.aligned.m8n8.x4.shared.b16 {%0,%1,%2,%3}, [%4];" \
                 : "=r"((R)[0]), "=r"((R)[1]), "=r"((R)[2]), "=r"((R)[3]) \
                 : "r"(addr))
#define LDM_X2(R, addr) \
    asm volatile("ldmatrix.sync.aligned.m8n8.x2.shared.b16 {%0,%1}, [%2];" \
                 : "=r"((R)[0]), "=r"((R)[1]) : "r"(addr))

#define MMA16816(C, A, B) \
    asm volatile("mma.sync.aligned.m16n8k16.row.col.f32.bf16.bf16.f32 " \
                 "{%0,%1,%2,%3}, {%4,%5,%6,%7}, {%8,%9}, {%0,%1,%2,%3};" \
                 : "+f"((C)[0]), "+f"((C)[1]), "+f"((C)[2]), "+f"((C)[3]) \
                 : "r"((A)[0]), "r"((A)[1]), "r"((A)[2]), "r"((A)[3]), \
                   "r"((B)[0]), "r"((B)[1]))

// ---------------- mma.sync GEMM: C[M,N] = (Ahi+Alo) @ (Bhi+Blo)^T -----------
// CTA tile 128x128, BK=32, double-buffered cp.async. 8 warps of 64x32.
// Padded smem rows (40 bf16 = 80B) -> conflict-free ldmatrix.
#define BKC   32
#define SAPD  40
#define TILE_ELE  (128 * SAPD)        // 5120 bf16 per tile
#define STAGE_ELE (4 * TILE_ELE)      // Ahi,Alo,Bhi,Blo
#define GEMM_SMEM_B (2 * STAGE_ELE * 2)   // 81920 bytes

__device__ __forceinline__ void gemm_load_stage(
    const __nv_bfloat16* __restrict__ Ahi, const __nv_bfloat16* __restrict__ Alo,
    const __nv_bfloat16* __restrict__ Bhi, const __nv_bfloat16* __restrict__ Blo,
    int K, int m0, int n0, int k0, uint32_t sdst, int tid) {
#pragma unroll
    for (int t = 0; t < 2; t++) {
        int idx = tid + t * 256;       // 0..511
        int row = idx >> 2;            // 0..127
        int c4  = idx & 3;             // 16B chunk within 64B row
        uint32_t so = sdst + (uint32_t)(row * SAPD + c4 * 8) * 2;
        size_t aoff = (size_t)(m0 + row) * K + k0 + c4 * 8;
        size_t boff = (size_t)(n0 + row) * K + k0 + c4 * 8;
        CP16(so,                    Ahi + aoff);
        CP16(so + TILE_ELE * 2,     Alo + aoff);
        CP16(so + 2 * TILE_ELE * 2, Bhi + boff);
        CP16(so + 3 * TILE_ELE * 2, Blo + boff);
    }
    CP_COMMIT();
}

__global__ __launch_bounds__(256)
void gemm_mma(const __nv_bfloat16* __restrict__ Ahi, const __nv_bfloat16* __restrict__ Alo,
              const __nv_bfloat16* __restrict__ Bhi, const __nv_bfloat16* __restrict__ Blo,
              float* __restrict__ C, int M, int N, int K) {
    extern __shared__ __nv_bfloat16 smb[];
    const int tid  = threadIdx.x;
    const int lane = tid & 31;
    const int wid  = tid >> 5;
    const int wm   = (wid & 1) * 64;    // warp M offset in CTA tile
    const int wn   = (wid >> 1) * 32;   // warp N offset
    const int m0 = blockIdx.y * 128;
    const int n0 = blockIdx.x * 128;
    const uint32_t sbase = s2u(smb);

    float acc[4][4][4];
#pragma unroll
    for (int mi = 0; mi < 4; mi++)
#pragma unroll
        for (int ni = 0; ni < 4; ni++)
#pragma unroll
            for (int r = 0; r < 4; r++) acc[mi][ni][r] = 0.f;

    const int nchunk = K / BKC;

    gemm_load_stage(Ahi, Alo, Bhi, Blo, K, m0, n0, 0, sbase, tid);

    for (int c = 0; c < nchunk; c++) {
        if (c + 1 < nchunk) {
            gemm_load_stage(Ahi, Alo, Bhi, Blo, K, m0, n0, (c + 1) * BKC,
                            sbase + (uint32_t)(((c + 1) & 1) * STAGE_ELE) * 2, tid);
            CP_WAIT1();
        } else {
            CP_WAIT0();
        }
        __syncthreads();

        const uint32_t sa = sbase + (uint32_t)((c & 1) * STAGE_ELE) * 2;
        const uint32_t sb = sa + 2 * TILE_ELE * 2;
#pragma unroll
        for (int ks = 0; ks < 2; ks++) {
            uint32_t ah[4][4], al[4][4];
#pragma unroll
            for (int mi = 0; mi < 4; mi++) {
                int r  = wm + mi * 16 + (lane & 15);
                int cc = ks * 16 + ((lane >> 4) << 3);
                uint32_t ad = sa + (uint32_t)(r * SAPD + cc) * 2;
                LDM_X4(ah[mi], ad);
                LDM_X4(al[mi], ad + TILE_ELE * 2);
            }
            uint32_t bh[4][2], bl[4][2];
#pragma unroll
            for (int ni = 0; ni < 4; ni++) {
                int r  = wn + ni * 8 + (lane & 7);
                int cc = ks * 16 + (((lane >> 3) & 1) << 3);
                uint32_t ad = sb + (uint32_t)(r * SAPD + cc) * 2;
                LDM_X2(bh[ni], ad);
                LDM_X2(bl[ni], ad + TILE_ELE * 2);
            }
#pragma unroll
            for (int mi = 0; mi < 4; mi++)
#pragma unroll
                for (int ni = 0; ni < 4; ni++) {
                    MMA16816(acc[mi][ni], ah[mi], bh[ni]);
                    MMA16816(acc[mi][ni], ah[mi], bl[ni]);
                    MMA16816(acc[mi][ni], al[mi], bh[ni]);
                }
        }
        __syncthreads();
    }

    // epilogue
    const int row0 = m0 + wm + (lane >> 2);
    const int col0 = n0 + wn + (lane & 3) * 2;
#pragma unroll
    for (int mi = 0; mi < 4; mi++) {
#pragma unroll
        for (int ni = 0; ni < 4; ni++) {
            float* p0 = C + (size_t)(row0 + mi * 16) * N + col0 + ni * 8;
            float* p1 = C + (size_t)(row0 + mi * 16 + 8) * N + col0 + ni * 8;
            *(float2*)p0 = make_float2(acc[mi][ni][0], acc[mi][ni][1]);
            *(float2*)p1 = make_float2(acc[mi][ni][2], acc[mi][ni][3]);
        }
    }
}

// ---------------- Flash attention (full past + 128 lookahead) ---------------
#define ABQ 128
#define ABK 64
#define ATT_SMEM_FLOATS (128*128 + 128*64 + 64*128 + 64*128)
#define ATT_SMEM_BYTES  (ATT_SMEM_FLOATS * 4)

__global__ __launch_bounds__(256, 1)
void attn_kernel(const float* __restrict__ Q, const float* __restrict__ Kg,
                 const float* __restrict__ Vg, float* __restrict__ O) {
    extern __shared__ float sm[];
    float* QsT = sm;                // [128 d][128 r]
    float* KsT = QsT + 128 * 128;   // [128 d][64 c]
    float* Vs  = KsT + 128 * 64;    // [64 k][128 d]
    float* PsT = Vs + 64 * 128;     // [64 k][128 r]

    const int tid = threadIdx.x;
    const int q0  = blockIdx.x * ABQ;
    const int h   = blockIdx.y;
    const int b   = blockIdx.z;
    const int kvh = h >> 2;
    const float scale = 0.08838834764831845f;  // 1/sqrt(128)

    {
        const float* Qb = Q + (((size_t)b * SS + q0) * HH + h) * DHD;
        int r = tid >> 1;
        int dbase = (tid & 1) * 64;
#pragma unroll
        for (int i = 0; i < 16; i++) {
            int d = dbase + i * 4;
            float4 v = *(const float4*)&Qb[(size_t)r * (HH * DHD) + d];
            QsT[(d + 0) * 128 + r] = v.x * scale;
            QsT[(d + 1) * 128 + r] = v.y * scale;
            QsT[(d + 2) * 128 + r] = v.z * scale;
            QsT[(d + 3) * 128 + r] = v.w * scale;
        }
    }

    const int ty = tid >> 4;
    const int tx = tid & 15;

    float m[8], l[8], acc[8][8];
#pragma unroll
    for (int i = 0; i < 8; i++) {
        m[i] = -1e30f; l[i] = 0.f;
#pragma unroll
        for (int j = 0; j < 8; j++) acc[i][j] = 0.f;
    }

    int kv_end = q0 + ABQ + WIN;
    if (kv_end > SS) kv_end = SS;

    for (int j0 = 0; j0 < kv_end; j0 += ABK) {
        __syncthreads();
        {
            const float* Kb = Kg + (((size_t)b * SS + j0) * KVH + kvh) * DHD;
            int c = tid >> 2;
            int dbase = (tid & 3) * 32;
#pragma unroll
            for (int i = 0; i < 8; i++) {
                int d = dbase + i * 4;
                float4 v = *(const float4*)&Kb[(size_t)c * (KVH * DHD) + d];
                KsT[(d + 0) * 64 + c] = v.x;
                KsT[(d + 1) * 64 + c] = v.y;
                KsT[(d + 2) * 64 + c] = v.z;
                KsT[(d + 3) * 64 + c] = v.w;
            }
            const float* Vb = Vg + (((size_t)b * SS + j0) * KVH + kvh) * DHD;
            int vr = tid >> 2;
            int vd = (tid & 3) * 32;
#pragma unroll
            for (int i = 0; i < 8; i++) {
                *(float4*)&Vs[vr * 128 + vd + i * 4] =
                    *(const float4*)&Vb[(size_t)vr * (KVH * DHD) + vd + i * 4];
            }
        }
        __syncthreads();

        float s[8][4];
#pragma unroll
        for (int i = 0; i < 8; i++)
#pragma unroll
            for (int j = 0; j < 4; j++) s[i][j] = 0.f;

#pragma unroll 4
        for (int d = 0; d < DHD; d++) {
            float a[8], bb[4];
            *(float4*)&a[0] = *(const float4*)&QsT[d * 128 + ty * 8];
            *(float4*)&a[4] = *(const float4*)&QsT[d * 128 + ty * 8 + 4];
            *(float4*)&bb[0] = *(const float4*)&KsT[d * 64 + tx * 4];
#pragma unroll
            for (int i = 0; i < 8; i++)
#pragma unroll
                for (int j = 0; j < 4; j++) s[i][j] += a[i] * bb[j];
        }

        if (j0 + ABK - 1 > q0 + WIN) {
#pragma unroll
            for (int i = 0; i < 8; i++) {
                int q = q0 + ty * 8 + i;
#pragma unroll
                for (int j = 0; j < 4; j++) {
                    int k = j0 + tx * 4 + j;
                    if (k > q + WIN) s[i][j] = -1e30f;
                }
            }
        }

#pragma unroll
        for (int i = 0; i < 8; i++) {
            float mx = fmaxf(fmaxf(s[i][0], s[i][1]), fmaxf(s[i][2], s[i][3]));
#pragma unroll
            for (int o = 8; o >= 1; o >>= 1)
                mx = fmaxf(mx, __shfl_xor_sync(0xffffffffu, mx, o));
            float mnew = fmaxf(m[i], mx);
            float p0 = __expf(s[i][0] - mnew);
            float p1 = __expf(s[i][1] - mnew);
            float p2 = __expf(s[i][2] - mnew);
            float p3 = __expf(s[i][3] - mnew);
            float ls = p0 + p1 + p2 + p3;
#pragma unroll
            for (int o = 8; o >= 1; o >>= 1)
                ls += __shfl_xor_sync(0xffffffffu, ls, o);
            float alpha = __expf(m[i] - mnew);
            m[i] = mnew;
            l[i] = l[i] * alpha + ls;
#pragma unroll
            for (int j = 0; j < 8; j++) acc[i][j] *= alpha;
            int r = ty * 8 + i;
            PsT[(tx * 4 + 0) * 128 + r] = p0;
            PsT[(tx * 4 + 1) * 128 + r] = p1;
            PsT[(tx * 4 + 2) * 128 + r] = p2;
            PsT[(tx * 4 + 3) * 128 + r] = p3;
        }
        __syncthreads();

#pragma unroll 2
        for (int kk = 0; kk < ABK; kk++) {
            float p[8], v[8];
            *(float4*)&p[0] = *(const float4*)&PsT[kk * 128 + ty * 8];
            *(float4*)&p[4] = *(const float4*)&PsT[kk * 128 + ty * 8 + 4];
            *(float4*)&v[0] = *(const float4*)&Vs[kk * 128 + tx * 8];
            *(float4*)&v[4] = *(const float4*)&Vs[kk * 128 + tx * 8 + 4];
#pragma unroll
            for (int i = 0; i < 8; i++)
#pragma unroll
                for (int j = 0; j < 8; j++) acc[i][j] += p[i] * v[j];
        }
    }

    float* Ob = O + (((size_t)b * SS + q0) * HH + h) * DHD;
#pragma unroll
    for (int i = 0; i < 8; i++) {
        float inv = 1.0f / l[i];
        int r = ty * 8 + i;
        float4 o0 = make_float4(acc[i][0] * inv, acc[i][1] * inv,
                                acc[i][2] * inv, acc[i][3] * inv);
        float4 o1 = make_float4(acc[i][4] * inv, acc[i][5] * inv,
                                acc[i][6] * inv, acc[i][7] * inv);
        float* orow = Ob + (size_t)r * (HH * DHD) + tx * 8;
        *(float4*)(orow) = o0;
        *(float4*)(orow + 4) = o1;
    }
}

// ---------------- launch ----------------------------------------------------
extern "C" void kernel_launch(void* const* d_in, const int* in_sizes, int n_in,
                              void* d_out, int out_size) {
    const float* x  = (const float*)d_in[0];
    const float* Wq = (const float*)d_in[1];
    const float* Wk = (const float*)d_in[2];
    const float* Wv = (const float*)d_in[3];
    const float* Wo = (const float*)d_in[4];
    float* out = (float*)d_out;

    void *pq, *pk, *pv, *pa;
    void *pxh, *pxl, *pqh, *pql, *pkh, *pkl, *pvh, *pvl, *poh, *pol, *pah, *pal;
    cudaGetSymbolAddress(&pq, g_q);
    cudaGetSymbolAddress(&pk, g_k);
    cudaGetSymbolAddress(&pv, g_v);
    cudaGetSymbolAddress(&pa, g_att);
    cudaGetSymbolAddress(&pxh, g_xhi);  cudaGetSymbolAddress(&pxl, g_xlo);
    cudaGetSymbolAddress(&pqh, g_wqhi); cudaGetSymbolAddress(&pql, g_wqlo);
    cudaGetSymbolAddress(&pkh, g_wkhi); cudaGetSymbolAddress(&pkl, g_wklo);
    cudaGetSymbolAddress(&pvh, g_wvhi); cudaGetSymbolAddress(&pvl, g_wvlo);
    cudaGetSymbolAddress(&poh, g_wohi); cudaGetSymbolAddress(&pol, g_wolo);
    cudaGetSymbolAddress(&pah, g_ahi);  cudaGetSymbolAddress(&pal, g_alo);
    float* Qb = (float*)pq;
    float* Kb = (float*)pk;
    float* Vb = (float*)pv;
    float* Ab = (float*)pa;

    cudaFuncSetAttribute(attn_kernel,
                         cudaFuncAttributeMaxDynamicSharedMemorySize,
                         ATT_SMEM_BYTES);
    cudaFuncSetAttribute(gemm_mma,
                         cudaFuncAttributeMaxDynamicSharedMemorySize,
                         GEMM_SMEM_B);

    // RoPE tables
    rope_tables_kernel<<<(SS * 64 + 255) / 256, 256>>>();

    // hi/lo splits of inputs and weights
    split_kernel<<<(MTOK * DD / 4 + 255) / 256, 256>>>(
        x, (__nv_bfloat16*)pxh, (__nv_bfloat16*)pxl, MTOK * DD / 4);
    split_kernel<<<(NQ * DD / 4 + 255) / 256, 256>>>(
        Wq, (__nv_bfloat16*)pqh, (__nv_bfloat16*)pql, NQ * DD / 4);
    split_kernel<<<(NKV * DD / 4 + 255) / 256, 256>>>(
        Wk, (__nv_bfloat16*)pkh, (__nv_bfloat16*)pkl, NKV * DD / 4);
    split_kernel<<<(NKV * DD / 4 + 255) / 256, 256>>>(
        Wv, (__nv_bfloat16*)pvh, (__nv_bfloat16*)pvl, NKV * DD / 4);
    split_kernel<<<(DD * NQ / 4 + 255) / 256, 256>>>(
        Wo, (__nv_bfloat16*)poh, (__nv_bfloat16*)pol, DD * NQ / 4);

    // QKV projections on mma.sync tensor cores
    gemm_mma<<<dim3(NQ / 128, MTOK / 128), 256, GEMM_SMEM_B>>>(
        (const __nv_bfloat16*)pxh, (const __nv_bfloat16*)pxl,
        (const __nv_bfloat16*)pqh, (const __nv_bfloat16*)pql,
        Qb, MTOK, NQ, DD);
    gemm_mma<<<dim3(NKV / 128, MTOK / 128), 256, GEMM_SMEM_B>>>(
        (const __nv_bfloat16*)pxh, (const __nv_bfloat16*)pxl,
        (const __nv_bfloat16*)pkh, (const __nv_bfloat16*)pkl,
        Kb, MTOK, NKV, DD);
    gemm_mma<<<dim3(NKV / 128, MTOK / 128), 256, GEMM_SMEM_B>>>(
        (const __nv_bfloat16*)pxh, (const __nv_bfloat16*)pxl,
        (const __nv_bfloat16*)pvh, (const __nv_bfloat16*)pvl,
        Vb, MTOK, NKV, DD);

    // RoPE (in place)
    rope_apply_kernel<<<(MTOK * HH * 64 + 255) / 256, 256>>>(Qb, HH);
    rope_apply_kernel<<<(MTOK * KVH * 64 + 255) / 256, 256>>>(Kb, KVH);

    // Attention (fp32 SIMT)
    attn_kernel<<<dim3(SS / ABQ, HH, BB), 256, ATT_SMEM_BYTES>>>(Qb, Kb, Vb, Ab);

    // Split attention output, then O projection on mma.sync
    split_kernel<<<(MTOK * NQ / 4 + 255) / 256, 256>>>(
        Ab, (__nv_bfloat16*)pah, (__nv_bfloat16*)pal, MTOK * NQ / 4);
    gemm_mma<<<dim3(DD / 128, MTOK / 128), 256, GEMM_SMEM_B>>>(
        (const __nv_bfloat16*)pah, (const __nv_bfloat16*)pal,
        (const __nv_bfloat16*)poh, (const __nv_bfloat16*)pol,
        out, MTOK, DD, NQ);
}

// round 6
// speedup vs baseline: 2.8981x; 1.8852x over previous
#include <cuda_runtime.h>
#include <cuda_bf16.h>
#include <math.h>
#include <stdint.h>

// Problem constants
#define BB    2
#define SS    2048
#define DD    2048
#define HH    16
#define KVH   4
#define DHD   128
#define WIN   128
#define MTOK  (BB*SS)          // 4096 tokens
#define NQ    (HH*DHD)         // 2048
#define NKV   (KVH*DHD)        // 512

// ---------------- scratch (device globals; no allocation allowed) ----------
__device__ __align__(256) float g_q[MTOK * NQ];      // 32 MB
__device__ __align__(256) float g_k[MTOK * NKV];     // 8 MB
__device__ __align__(256) float g_v[MTOK * NKV];     // 8 MB
__device__ __align__(256) float g_att[MTOK * NQ];    // 32 MB
__device__ float g_cos[SS * 64];
__device__ float g_sin[SS * 64];
// hi/lo bf16 splits (GEMM operands)
__device__ __align__(256) __nv_bfloat16 g_xhi[MTOK * DD],  g_xlo[MTOK * DD];
__device__ __align__(256) __nv_bfloat16 g_wqhi[NQ * DD],   g_wqlo[NQ * DD];
__device__ __align__(256) __nv_bfloat16 g_wkhi[NKV * DD],  g_wklo[NKV * DD];
__device__ __align__(256) __nv_bfloat16 g_wvhi[NKV * DD],  g_wvlo[NKV * DD];
__device__ __align__(256) __nv_bfloat16 g_wohi[DD * NQ],   g_wolo[DD * NQ];
__device__ __align__(256) __nv_bfloat16 g_ahi[MTOK * NQ],  g_alo[MTOK * NQ];
// hi/lo bf16 splits (attention operands, post-RoPE)
__device__ __align__(256) __nv_bfloat16 g_qah[MTOK * NQ],  g_qal[MTOK * NQ];
__device__ __align__(256) __nv_bfloat16 g_kah[MTOK * NKV], g_kal[MTOK * NKV];
__device__ __align__(256) __nv_bfloat16 g_vah[MTOK * NKV], g_val[MTOK * NKV];

// ---------------- RoPE tables ----------------------------------------------
__global__ void rope_tables_kernel() {
    int idx = blockIdx.x * blockDim.x + threadIdx.x;
    if (idx >= SS * 64) return;
    int s = idx >> 6;
    int j = idx & 63;
    double freq = exp(-((double)(2 * j) / 128.0) * 9.210340371976184); // ln(10000)
    double a = (double)s * freq;
    g_cos[idx] = (float)cos(a);
    g_sin[idx] = (float)sin(a);
}

// ---------------- RoPE apply ------------------------------------------------
__global__ void rope_apply_kernel(float* __restrict__ t, int nheads) {
    int idx = blockIdx.x * blockDim.x + threadIdx.x;
    int total = MTOK * nheads * 64;
    if (idx >= total) return;
    int i   = idx & 63;
    int h   = (idx >> 6) % nheads;
    int tok = idx / (64 * nheads);
    int pos = tok & (SS - 1);
    float* p = t + ((size_t)tok * nheads + h) * DHD;
    float x0 = p[i];
    float x1 = p[i + 64];
    int j = i >> 1;
    float c0 = g_cos[pos * 64 + j],      s0 = g_sin[pos * 64 + j];
    float c1 = g_cos[pos * 64 + 32 + j], s1 = g_sin[pos * 64 + 32 + j];
    p[i]      = x0 * c0 - x1 * s0;
    p[i + 64] = x1 * c1 + x0 * s1;
}

// ---------------- hi/lo bf16 split (optional scale) --------------------------
__global__ void split_kernel(const float* __restrict__ src,
                             __nv_bfloat16* __restrict__ hi,
                             __nv_bfloat16* __restrict__ lo, int n4, float scl) {
    int i = blockIdx.x * blockDim.x + threadIdx.x;
    if (i >= n4) return;
    float4 v = ((const float4*)src)[i];
    v.x *= scl; v.y *= scl; v.z *= scl; v.w *= scl;
    __nv_bfloat16 h0 = __float2bfloat16(v.x);
    __nv_bfloat16 h1 = __float2bfloat16(v.y);
    __nv_bfloat16 h2 = __float2bfloat16(v.z);
    __nv_bfloat16 h3 = __float2bfloat16(v.w);
    __nv_bfloat16 l0 = __float2bfloat16(v.x - __bfloat162float(h0));
    __nv_bfloat16 l1 = __float2bfloat16(v.y - __bfloat162float(h1));
    __nv_bfloat16 l2 = __float2bfloat16(v.z - __bfloat162float(h2));
    __nv_bfloat16 l3 = __float2bfloat16(v.w - __bfloat162float(h3));
    __nv_bfloat162* ph = (__nv_bfloat162*)hi;
    __nv_bfloat162* pl = (__nv_bfloat162*)lo;
    ph[2 * i]     = __nv_bfloat162(h0, h1);
    ph[2 * i + 1] = __nv_bfloat162(h2, h3);
    pl[2 * i]     = __nv_bfloat162(l0, l1);
    pl[2 * i + 1] = __nv_bfloat162(l2, l3);
}

// ---------------- PTX helpers (non-'a' features only) ------------------------
__device__ __forceinline__ uint32_t s2u(const void* p) {
    uint32_t a;
    asm("{ .reg .u64 t; cvta.to.shared.u64 t, %1; cvt.u32.u64 %0, t; }"
        : "=r"(a) : "l"(p));
    return a;
}

#define CP16(saddr, gptr) \
    asm volatile("cp.async.cg.shared.global [%0], [%1], 16;" \
                 :: "r"(saddr), "l"(gptr))
#define CP_COMMIT() asm volatile("cp.async.commit_group;" ::: "memory")
#define CP_WAIT0()  asm volatile("cp.async.wait_group 0;" ::: "memory")
#define CP_WAIT1()  asm volatile("cp.async.wait_group 1;" ::: "memory")

#define LDM_X4(R, addr) \
    asm volatile("ldmatrix.sync.aligned.m8n8.x4.shared.b16 {%0,%1,%2,%3}, [%4];" \
                 : "=r"((R)[0]), "=r"((R)[1]), "=r"((R)[2]), "=r"((R)[3]) \
                 : "r"(addr))
#define LDM_X4_T(R, addr) \
    asm volatile("ldmatrix.sync.aligned.m8n8.x4.trans.shared.b16 {%0,%1,%2,%3}, [%4];" \
                 : "=r"((R)[0]), "=r"((R)[1]), "=r"((R)[2]), "=r"((R)[3]) \
                 : "r"(addr))
#define LDM_X2(R, addr) \
    asm volatile("ldmatrix.sync.aligned.m8n8.x2.shared.b16 {%0,%1}, [%2];" \
                 : "=r"((R)[0]), "=r"((R)[1]) : "r"(addr))

#define MMA16816(C, A, B) \
    asm volatile("mma.sync.aligned.m16n8k16.row.col.f32.bf16.bf16.f32 " \
                 "{%0,%1,%2,%3}, {%4,%5,%6,%7}, {%8,%9}, {%0,%1,%2,%3};" \
                 : "+f"((C)[0]), "+f"((C)[1]), "+f"((C)[2]), "+f"((C)[3]) \
                 : "r"((A)[0]), "r"((A)[1]), "r"((A)[2]), "r"((A)[3]), \
                   "r"((B)[0]), "r"((B)[1]))

__device__ __forceinline__ uint32_t bf2(float lo, float hi) {
    uint32_t r;
    asm("cvt.rn.bf16x2.f32 %0, %1, %2;" : "=r"(r) : "f"(hi), "f"(lo));
    return r;
}
__device__ __forceinline__ float bfres(float x) {
    return x - __bfloat162float(__float2bfloat16(x));
}

// ---------------- mma.sync GEMM: C[M,N] = (Ahi+Alo) @ (Bhi+Blo)^T -----------
#define BKC   32
#define SAPD  40
#define TILE_ELE  (128 * SAPD)
#define STAGE_ELE (4 * TILE_ELE)
#define GEMM_SMEM_B (2 * STAGE_ELE * 2)   // 81920 bytes

__device__ __forceinline__ void gemm_load_stage(
    const __nv_bfloat16* __restrict__ Ahi, const __nv_bfloat16* __restrict__ Alo,
    const __nv_bfloat16* __restrict__ Bhi, const __nv_bfloat16* __restrict__ Blo,
    int K, int m0, int n0, int k0, uint32_t sdst, int tid) {
#pragma unroll
    for (int t = 0; t < 2; t++) {
        int idx = tid + t * 256;
        int row = idx >> 2;
        int c4  = idx & 3;
        uint32_t so = sdst + (uint32_t)(row * SAPD + c4 * 8) * 2;
        size_t aoff = (size_t)(m0 + row) * K + k0 + c4 * 8;
        size_t boff = (size_t)(n0 + row) * K + k0 + c4 * 8;
        CP16(so,                    Ahi + aoff);
        CP16(so + TILE_ELE * 2,     Alo + aoff);
        CP16(so + 2 * TILE_ELE * 2, Bhi + boff);
        CP16(so + 3 * TILE_ELE * 2, Blo + boff);
    }
    CP_COMMIT();
}

__global__ __launch_bounds__(256)
void gemm_mma(const __nv_bfloat16* __restrict__ Ahi, const __nv_bfloat16* __restrict__ Alo,
              const __nv_bfloat16* __restrict__ Bhi, const __nv_bfloat16* __restrict__ Blo,
              float* __restrict__ C, int M, int N, int K) {
    extern __shared__ __nv_bfloat16 smb[];
    const int tid  = threadIdx.x;
    const int lane = tid & 31;
    const int wid  = tid >> 5;
    const int wm   = (wid & 1) * 64;
    const int wn   = (wid >> 1) * 32;
    const int m0 = blockIdx.y * 128;
    const int n0 = blockIdx.x * 128;
    const uint32_t sbase = s2u(smb);

    float acc[4][4][4];
#pragma unroll
    for (int mi = 0; mi < 4; mi++)
#pragma unroll
        for (int ni = 0; ni < 4; ni++)
#pragma unroll
            for (int r = 0; r < 4; r++) acc[mi][ni][r] = 0.f;

    const int nchunk = K / BKC;
    gemm_load_stage(Ahi, Alo, Bhi, Blo, K, m0, n0, 0, sbase, tid);

    for (int c = 0; c < nchunk; c++) {
        if (c + 1 < nchunk) {
            gemm_load_stage(Ahi, Alo, Bhi, Blo, K, m0, n0, (c + 1) * BKC,
                            sbase + (uint32_t)(((c + 1) & 1) * STAGE_ELE) * 2, tid);
            CP_WAIT1();
        } else {
            CP_WAIT0();
        }
        __syncthreads();

        const uint32_t sa = sbase + (uint32_t)((c & 1) * STAGE_ELE) * 2;
        const uint32_t sb = sa + 2 * TILE_ELE * 2;
#pragma unroll
        for (int ks = 0; ks < 2; ks++) {
            uint32_t ah[4][4], al[4][4];
#pragma unroll
            for (int mi = 0; mi < 4; mi++) {
                int r  = wm + mi * 16 + (lane & 15);
                int cc = ks * 16 + ((lane >> 4) << 3);
                uint32_t ad = sa + (uint32_t)(r * SAPD + cc) * 2;
                LDM_X4(ah[mi], ad);
                LDM_X4(al[mi], ad + TILE_ELE * 2);
            }
            uint32_t bh[4][2], bl[4][2];
#pragma unroll
            for (int ni = 0; ni < 4; ni++) {
                int r  = wn + ni * 8 + (lane & 7);
                int cc = ks * 16 + (((lane >> 3) & 1) << 3);
                uint32_t ad = sb + (uint32_t)(r * SAPD + cc) * 2;
                LDM_X2(bh[ni], ad);
                LDM_X2(bl[ni], ad + TILE_ELE * 2);
            }
#pragma unroll
            for (int mi = 0; mi < 4; mi++)
#pragma unroll
                for (int ni = 0; ni < 4; ni++) {
                    MMA16816(acc[mi][ni], ah[mi], bh[ni]);
                    MMA16816(acc[mi][ni], ah[mi], bl[ni]);
                    MMA16816(acc[mi][ni], al[mi], bh[ni]);
                }
        }
        __syncthreads();
    }

    const int row0 = m0 + wm + (lane >> 2);
    const int col0 = n0 + wn + (lane & 3) * 2;
#pragma unroll
    for (int mi = 0; mi < 4; mi++) {
#pragma unroll
        for (int ni = 0; ni < 4; ni++) {
            float* p0 = C + (size_t)(row0 + mi * 16) * N + col0 + ni * 8;
            float* p1 = C + (size_t)(row0 + mi * 16 + 8) * N + col0 + ni * 8;
            *(float2*)p0 = make_float2(acc[mi][ni][0], acc[mi][ni][1]);
            *(float2*)p1 = make_float2(acc[mi][ni][2], acc[mi][ni][3]);
        }
    }
}

// ---------------- Flash attention on mma.sync --------------------------------
// CTA: 128 q x 64 k per iter; 8 warps x 16 q-rows. hi/lo split everywhere.
// smem pitch 136 halfs -> conflict-free ldmatrix (incl. trans for V).
#define AP   136
#define QT   (128 * AP)            // 17408 halfs per Q tile
#define KVT  (64 * AP)             // 8704 halfs per K/V tile
#define STG  (4 * KVT)             // KH,KL,VH,VL
#define ATT_SMEM_B ((2 * QT + 2 * STG) * 2)   // 208896 bytes

__device__ __forceinline__ void attn_load_kv(
    const __nv_bfloat16* __restrict__ Kh, const __nv_bfloat16* __restrict__ Kl,
    const __nv_bfloat16* __restrict__ Vh, const __nv_bfloat16* __restrict__ Vl,
    int b, int kvh, int j0, uint32_t base, int tid) {
#pragma unroll
    for (int t = 0; t < 4; t++) {
        int idx = tid + t * 256;         // 0..1023
        int row = idx >> 4;              // 0..63
        int c   = idx & 15;
        uint32_t off = (uint32_t)(row * AP + c * 8) * 2;
        size_t g = ((size_t)(b * SS + j0 + row) * KVH + kvh) * DHD + c * 8;
        CP16(base + off,               Kh + g);
        CP16(base + KVT * 2 + off,     Kl + g);
        CP16(base + 2 * KVT * 2 + off, Vh + g);
        CP16(base + 3 * KVT * 2 + off, Vl + g);
    }
    CP_COMMIT();
}

__global__ __launch_bounds__(256, 1)
void attn_mma(const __nv_bfloat16* __restrict__ Qh, const __nv_bfloat16* __restrict__ Ql,
              const __nv_bfloat16* __restrict__ Kh, const __nv_bfloat16* __restrict__ Kl,
              const __nv_bfloat16* __restrict__ Vh, const __nv_bfloat16* __restrict__ Vl,
              float* __restrict__ O) {
    extern __shared__ __nv_bfloat16 sa[];
    const int tid  = threadIdx.x;
    const int lane = tid & 31;
    const int wid  = tid >> 5;
    // longest CTAs (largest q0) first to reduce wave tail
    const int q0   = (gridDim.x - 1 - blockIdx.x) * 128;
    const int h    = blockIdx.y;
    const int b    = blockIdx.z;
    const int kvh  = h >> 2;
    const uint32_t sb = s2u(sa);
    const uint32_t QHo = sb;
    const uint32_t QLo = sb + QT * 2;

    // load Q tiles (hi/lo) via cp.async
    {
        const __nv_bfloat16* qgh = Qh + (((size_t)b * SS + q0) * HH + h) * DHD;
        const __nv_bfloat16* qgl = Ql + (((size_t)b * SS + q0) * HH + h) * DHD;
#pragma unroll
        for (int t = 0; t < 8; t++) {
            int idx = tid + t * 256;     // 0..2047
            int row = idx >> 4;          // 0..127
            int c   = idx & 15;
            uint32_t off = (uint32_t)(row * AP + c * 8) * 2;
            size_t g = (size_t)row * (HH * DHD) + c * 8;
            CP16(QHo + off, qgh + g);
            CP16(QLo + off, qgl + g);
        }
        CP_COMMIT();
    }

    const int kv_end = min(q0 + 256, SS);
    const int nblk   = kv_end >> 6;
    const uint32_t stg0 = sb + 2 * QT * 2;

    attn_load_kv(Kh, Kl, Vh, Vl, b, kvh, 0, stg0, tid);

    float oacc[16][4];
#pragma unroll
    for (int df = 0; df < 16; df++)
#pragma unroll
        for (int r = 0; r < 4; r++) oacc[df][r] = 0.f;
    float m0r = -1e30f, m1r = -1e30f, l0r = 0.f, l1r = 0.f;

    const int r0 = wid * 16;

    for (int blk = 0; blk < nblk; blk++) {
        if (blk + 1 < nblk) {
            attn_load_kv(Kh, Kl, Vh, Vl, b, kvh, (blk + 1) * 64,
                         stg0 + (uint32_t)(((blk + 1) & 1) * STG) * 2, tid);
            CP_WAIT1();
        } else {
            CP_WAIT0();
        }
        __syncthreads();

        const uint32_t kb = stg0 + (uint32_t)((blk & 1) * STG) * 2;   // Khi
        const uint32_t vb = kb + 2 * KVT * 2;                          // Vhi

        // ---- S = Q K^T ----
        float sacc[8][4];
#pragma unroll
        for (int nf = 0; nf < 8; nf++)
#pragma unroll
            for (int r = 0; r < 4; r++) sacc[nf][r] = 0.f;

#pragma unroll
        for (int ks = 0; ks < 8; ks++) {
            uint32_t ah[4], al[4];
            uint32_t qa = QHo + (uint32_t)((r0 + (lane & 15)) * AP +
                                           ks * 16 + ((lane >> 4) << 3)) * 2;
            LDM_X4(ah, qa);
            LDM_X4(al, qa + QT * 2);
#pragma unroll
            for (int np = 0; np < 4; np++) {
                uint32_t bh[4], bl[4];
                uint32_t ba = kb + (uint32_t)((np * 16 + (lane & 7) + ((lane >> 4) & 1) * 8) * AP +
                                              ks * 16 + ((lane >> 3) & 1) * 8) * 2;
                LDM_X4(bh, ba);
                LDM_X4(bl, ba + KVT * 2);
                MMA16816(sacc[2 * np],     ah, &bh[0]);
                MMA16816(sacc[2 * np],     ah, &bl[0]);
                MMA16816(sacc[2 * np],     al, &bh[0]);
                MMA16816(sacc[2 * np + 1], ah, &bh[2]);
                MMA16816(sacc[2 * np + 1], ah, &bl[2]);
                MMA16816(sacc[2 * np + 1], al, &bh[2]);
            }
        }

        // ---- mask ----
        const int j0 = blk * 64;
        if (j0 + 63 > q0 + WIN) {
            const int rq = q0 + r0 + (lane >> 2);
#pragma unroll
            for (int nf = 0; nf < 8; nf++) {
#pragma unroll
                for (int e = 0; e < 2; e++) {
                    int k = j0 + nf * 8 + (lane & 3) * 2 + e;
                    if (k > rq + WIN)     sacc[nf][e]     = -1e30f;
                    if (k > rq + 8 + WIN) sacc[nf][2 + e] = -1e30f;
                }
            }
        }

        // ---- online softmax ----
        float mx0 = -1e30f, mx1 = -1e30f;
#pragma unroll
        for (int nf = 0; nf < 8; nf++) {
            mx0 = fmaxf(mx0, fmaxf(sacc[nf][0], sacc[nf][1]));
            mx1 = fmaxf(mx1, fmaxf(sacc[nf][2], sacc[nf][3]));
        }
        mx0 = fmaxf(mx0, __shfl_xor_sync(0xffffffffu, mx0, 1));
        mx0 = fmaxf(mx0, __shfl_xor_sync(0xffffffffu, mx0, 2));
        mx1 = fmaxf(mx1, __shfl_xor_sync(0xffffffffu, mx1, 1));
        mx1 = fmaxf(mx1, __shfl_xor_sync(0xffffffffu, mx1, 2));
        float mn0 = fmaxf(m0r, mx0), mn1 = fmaxf(m1r, mx1);
        float a0 = __expf(m0r - mn0), a1 = __expf(m1r - mn1);
        m0r = mn0; m1r = mn1;
        float s0 = 0.f, s1 = 0.f;
#pragma unroll
        for (int nf = 0; nf < 8; nf++) {
            sacc[nf][0] = __expf(sacc[nf][0] - mn0);
            sacc[nf][1] = __expf(sacc[nf][1] - mn0);
            sacc[nf][2] = __expf(sacc[nf][2] - mn1);
            sacc[nf][3] = __expf(sacc[nf][3] - mn1);
            s0 += sacc[nf][0] + sacc[nf][1];
            s1 += sacc[nf][2] + sacc[nf][3];
        }
        s0 += __shfl_xor_sync(0xffffffffu, s0, 1);
        s0 += __shfl_xor_sync(0xffffffffu, s0, 2);
        s1 += __shfl_xor_sync(0xffffffffu, s1, 1);
        s1 += __shfl_xor_sync(0xffffffffu, s1, 2);
        l0r = l0r * a0 + s0;
        l1r = l1r * a1 + s1;
#pragma unroll
        for (int df = 0; df < 16; df++) {
            oacc[df][0] *= a0; oacc[df][1] *= a0;
            oacc[df][2] *= a1; oacc[df][3] *= a1;
        }

        // ---- O += P V ----
#pragma unroll
        for (int kk = 0; kk < 4; kk++) {
            const float* f0 = sacc[2 * kk];
            const float* f1 = sacc[2 * kk + 1];
            uint32_t ph[4], pl[4];
            ph[0] = bf2(f0[0], f0[1]); ph[1] = bf2(f0[2], f0[3]);
            ph[2] = bf2(f1[0], f1[1]); ph[3] = bf2(f1[2], f1[3]);
            pl[0] = bf2(bfres(f0[0]), bfres(f0[1]));
            pl[1] = bf2(bfres(f0[2]), bfres(f0[3]));
            pl[2] = bf2(bfres(f1[0]), bfres(f1[1]));
            pl[3] = bf2(bfres(f1[2]), bfres(f1[3]));
#pragma unroll
            for (int dp = 0; dp < 8; dp++) {
                uint32_t bvh[4], bvl[4];
                uint32_t va = vb + (uint32_t)((kk * 16 + (lane & 15)) * AP +
                                              dp * 16 + ((lane >> 4) << 3)) * 2;
                LDM_X4_T(bvh, va);
                LDM_X4_T(bvl, va + KVT * 2);
                MMA16816(oacc[2 * dp],     ph, &bvh[0]);
                MMA16816(oacc[2 * dp],     ph, &bvl[0]);
                MMA16816(oacc[2 * dp],     pl, &bvh[0]);
                MMA16816(oacc[2 * dp + 1], ph, &bvh[2]);
                MMA16816(oacc[2 * dp + 1], ph, &bvl[2]);
                MMA16816(oacc[2 * dp + 1], pl, &bvh[2]);
            }
        }
        __syncthreads();
    }

    // ---- epilogue ----
    const float inv0 = 1.0f / l0r;
    const float inv1 = 1.0f / l1r;
    const int rq = q0 + r0 + (lane >> 2);
    float* Ob0 = O + (((size_t)b * SS + rq) * HH + h) * DHD;
    float* Ob1 = Ob0 + (size_t)8 * HH * DHD;
#pragma unroll
    for (int df = 0; df < 16; df++) {
        int col = df * 8 + (lane & 3) * 2;
        *(float2*)(Ob0 + col) = make_float2(oacc[df][0] * inv0, oacc[df][1] * inv0);
        *(float2*)(Ob1 + col) = make_float2(oacc[df][2] * inv1, oacc[df][3] * inv1);
    }
}

// ---------------- launch ----------------------------------------------------
extern "C" void kernel_launch(void* const* d_in, const int* in_sizes, int n_in,
                              void* d_out, int out_size) {
    const float* x  = (const float*)d_in[0];
    const float* Wq = (const float*)d_in[1];
    const float* Wk = (const float*)d_in[2];
    const float* Wv = (const float*)d_in[3];
    const float* Wo = (const float*)d_in[4];
    float* out = (float*)d_out;

    void *pq, *pk, *pv, *pa;
    void *pxh, *pxl, *pqh, *pql, *pkh, *pkl, *pvh, *pvl, *poh, *pol, *pah, *pal;
    void *aqh, *aql, *akh, *akl, *avh, *avl;
    cudaGetSymbolAddress(&pq, g_q);
    cudaGetSymbolAddress(&pk, g_k);
    cudaGetSymbolAddress(&pv, g_v);
    cudaGetSymbolAddress(&pa, g_att);
    cudaGetSymbolAddress(&pxh, g_xhi);  cudaGetSymbolAddress(&pxl, g_xlo);
    cudaGetSymbolAddress(&pqh, g_wqhi); cudaGetSymbolAddress(&pql, g_wqlo);
    cudaGetSymbolAddress(&pkh, g_wkhi); cudaGetSymbolAddress(&pkl, g_wklo);
    cudaGetSymbolAddress(&pvh, g_wvhi); cudaGetSymbolAddress(&pvl, g_wvlo);
    cudaGetSymbolAddress(&poh, g_wohi); cudaGetSymbolAddress(&pol, g_wolo);
    cudaGetSymbolAddress(&pah, g_ahi);  cudaGetSymbolAddress(&pal, g_alo);
    cudaGetSymbolAddress(&aqh, g_qah);  cudaGetSymbolAddress(&aql, g_qal);
    cudaGetSymbolAddress(&akh, g_kah);  cudaGetSymbolAddress(&akl, g_kal);
    cudaGetSymbolAddress(&avh, g_vah);  cudaGetSymbolAddress(&avl, g_val);
    float* Qb = (float*)pq;
    float* Kb = (float*)pk;
    float* Vb = (float*)pv;
    float* Ab = (float*)pa;

    cudaFuncSetAttribute(gemm_mma,
                         cudaFuncAttributeMaxDynamicSharedMemorySize, GEMM_SMEM_B);
    cudaFuncSetAttribute(attn_mma,
                         cudaFuncAttributeMaxDynamicSharedMemorySize, ATT_SMEM_B);

    // RoPE tables
    rope_tables_kernel<<<(SS * 64 + 255) / 256, 256>>>();

    // hi/lo splits of inputs and weights
    split_kernel<<<(MTOK * DD / 4 + 255) / 256, 256>>>(
        x, (__nv_bfloat16*)pxh, (__nv_bfloat16*)pxl, MTOK * DD / 4, 1.0f);
    split_kernel<<<(NQ * DD / 4 + 255) / 256, 256>>>(
        Wq, (__nv_bfloat16*)pqh, (__nv_bfloat16*)pql, NQ * DD / 4, 1.0f);
    split_kernel<<<(NKV * DD / 4 + 255) / 256, 256>>>(
        Wk, (__nv_bfloat16*)pkh, (__nv_bfloat16*)pkl, NKV * DD / 4, 1.0f);
    split_kernel<<<(NKV * DD / 4 + 255) / 256, 256>>>(
        Wv, (__nv_bfloat16*)pvh, (__nv_bfloat16*)pvl, NKV * DD / 4, 1.0f);
    split_kernel<<<(DD * NQ / 4 + 255) / 256, 256>>>(
        Wo, (__nv_bfloat16*)poh, (__nv_bfloat16*)pol, DD * NQ / 4, 1.0f);

    // QKV projections
    gemm_mma<<<dim3(NQ / 128, MTOK / 128), 256, GEMM_SMEM_B>>>(
        (const __nv_bfloat16*)pxh, (const __nv_bfloat16*)pxl,
        (const __nv_bfloat16*)pqh, (const __nv_bfloat16*)pql,
        Qb, MTOK, NQ, DD);
    gemm_mma<<<dim3(NKV / 128, MTOK / 128), 256, GEMM_SMEM_B>>>(
        (const __nv_bfloat16*)pxh, (const __nv_bfloat16*)pxl,
        (const __nv_bfloat16*)pkh, (const __nv_bfloat16*)pkl,
        Kb, MTOK, NKV, DD);
    gemm_mma<<<dim3(NKV / 128, MTOK / 128), 256, GEMM_SMEM_B>>>(
        (const __nv_bfloat16*)pxh, (const __nv_bfloat16*)pxl,
        (const __nv_bfloat16*)pvh, (const __nv_bfloat16*)pvl,
        Vb, MTOK, NKV, DD);

    // RoPE (in place, fp32)
    rope_apply_kernel<<<(MTOK * HH * 64 + 255) / 256, 256>>>(Qb, HH);
    rope_apply_kernel<<<(MTOK * KVH * 64 + 255) / 256, 256>>>(Kb, KVH);

    // split post-RoPE Q (scale folded), K, V for attention
    const float scale = 0.08838834764831845f;   // 1/sqrt(128)
    split_kernel<<<(MTOK * NQ / 4 + 255) / 256, 256>>>(
        Qb, (__nv_bfloat16*)aqh, (__nv_bfloat16*)aql, MTOK * NQ / 4, scale);
    split_kernel<<<(MTOK * NKV / 4 + 255) / 256, 256>>>(
        Kb, (__nv_bfloat16*)akh, (__nv_bfloat16*)akl, MTOK * NKV / 4, 1.0f);
    split_kernel<<<(MTOK * NKV / 4 + 255) / 256, 256>>>(
        Vb, (__nv_bfloat16*)avh, (__nv_bfloat16*)avl, MTOK * NKV / 4, 1.0f);

    // Attention on tensor cores
    attn_mma<<<dim3(SS / 128, HH, BB), 256, ATT_SMEM_B>>>(
        (const __nv_bfloat16*)aqh, (const __nv_bfloat16*)aql,
        (const __nv_bfloat16*)akh, (const __nv_bfloat16*)akl,
        (const __nv_bfloat16*)avh, (const __nv_bfloat16*)avl, Ab);

    // Split attention output, then O projection
    split_kernel<<<(MTOK * NQ / 4 + 255) / 256, 256>>>(
        Ab, (__nv_bfloat16*)pah, (__nv_bfloat16*)pal, MTOK * NQ / 4, 1.0f);
    gemm_mma<<<dim3(DD / 128, MTOK / 128), 256, GEMM_SMEM_B>>>(
        (const __nv_bfloat16*)pah, (const __nv_bfloat16*)pal,
        (const __nv_bfloat16*)poh, (const __nv_bfloat16*)pol,
        out, MTOK, DD, NQ);
}

// round 7
// speedup vs baseline: 2.9602x; 1.0214x over previous
#include <cuda_runtime.h>
#include <cuda_bf16.h>
#include <math.h>
#include <stdint.h>

// Problem constants
#define BB    2
#define SS    2048
#define DD    2048
#define HH    16
#define KVH   4
#define DHD   128
#define WIN   128
#define MTOK  (BB*SS)          // 4096 tokens
#define NQ    (HH*DHD)         // 2048
#define NKV   (KVH*DHD)        // 512

// ---------------- scratch (device globals; no allocation allowed) ----------
__device__ __align__(256) float g_q[MTOK * NQ];      // 32 MB (fp32, pre-rope)
__device__ __align__(256) float g_k[MTOK * NKV];     // 8 MB  (fp32, pre-rope)
__device__ float g_cos[SS * 64];
__device__ float g_sin[SS * 64];
// hi/lo bf16 splits (GEMM operands)
__device__ __align__(256) __nv_bfloat16 g_xhi[MTOK * DD],  g_xlo[MTOK * DD];
__device__ __align__(256) __nv_bfloat16 g_wqhi[NQ * DD],   g_wqlo[NQ * DD];
__device__ __align__(256) __nv_bfloat16 g_wkhi[NKV * DD],  g_wklo[NKV * DD];
__device__ __align__(256) __nv_bfloat16 g_wvhi[NKV * DD],  g_wvlo[NKV * DD];
__device__ __align__(256) __nv_bfloat16 g_wohi[DD * NQ],   g_wolo[DD * NQ];
__device__ __align__(256) __nv_bfloat16 g_ahi[MTOK * NQ],  g_alo[MTOK * NQ];
// attention operands (post-RoPE hi/lo)
__device__ __align__(256) __nv_bfloat16 g_qah[MTOK * NQ],  g_qal[MTOK * NQ];
__device__ __align__(256) __nv_bfloat16 g_kah[MTOK * NKV], g_kal[MTOK * NKV];
__device__ __align__(256) __nv_bfloat16 g_vah[MTOK * NKV], g_val[MTOK * NKV];

// ---------------- RoPE tables ----------------------------------------------
__global__ void rope_tables_kernel() {
    int idx = blockIdx.x * blockDim.x + threadIdx.x;
    if (idx >= SS * 64) return;
    int s = idx >> 6;
    int j = idx & 63;
    double freq = exp(-((double)(2 * j) / 128.0) * 9.210340371976184); // ln(10000)
    double a = (double)s * freq;
    g_cos[idx] = (float)cos(a);
    g_sin[idx] = (float)sin(a);
}

// ---------------- fused RoPE + hi/lo split ----------------------------------
__global__ void rope_split_kernel(const float* __restrict__ src,
                                  __nv_bfloat16* __restrict__ hi,
                                  __nv_bfloat16* __restrict__ lo,
                                  int nheads, float scl) {
    int idx = blockIdx.x * blockDim.x + threadIdx.x;
    int total = MTOK * nheads * 64;
    if (idx >= total) return;
    int i   = idx & 63;
    int h   = (idx >> 6) % nheads;
    int tok = idx / (64 * nheads);
    int pos = tok & (SS - 1);
    size_t base = ((size_t)tok * nheads + h) * DHD;
    const float* p = src + base;
    float x0 = p[i];
    float x1 = p[i + 64];
    int j = i >> 1;
    float c0 = g_cos[pos * 64 + j],      s0 = g_sin[pos * 64 + j];
    float c1 = g_cos[pos * 64 + 32 + j], s1 = g_sin[pos * 64 + 32 + j];
    float y0 = (x0 * c0 - x1 * s0) * scl;
    float y1 = (x1 * c1 + x0 * s1) * scl;
    __nv_bfloat16 h0 = __float2bfloat16(y0);
    __nv_bfloat16 h1 = __float2bfloat16(y1);
    hi[base + i]      = h0;
    hi[base + i + 64] = h1;
    lo[base + i]      = __float2bfloat16(y0 - __bfloat162float(h0));
    lo[base + i + 64] = __float2bfloat16(y1 - __bfloat162float(h1));
}

// ---------------- hi/lo bf16 split ------------------------------------------
__global__ void split_kernel(const float* __restrict__ src,
                             __nv_bfloat16* __restrict__ hi,
                             __nv_bfloat16* __restrict__ lo, int n4) {
    int i = blockIdx.x * blockDim.x + threadIdx.x;
    if (i >= n4) return;
    float4 v = ((const float4*)src)[i];
    __nv_bfloat16 h0 = __float2bfloat16(v.x);
    __nv_bfloat16 h1 = __float2bfloat16(v.y);
    __nv_bfloat16 h2 = __float2bfloat16(v.z);
    __nv_bfloat16 h3 = __float2bfloat16(v.w);
    __nv_bfloat16 l0 = __float2bfloat16(v.x - __bfloat162float(h0));
    __nv_bfloat16 l1 = __float2bfloat16(v.y - __bfloat162float(h1));
    __nv_bfloat16 l2 = __float2bfloat16(v.z - __bfloat162float(h2));
    __nv_bfloat16 l3 = __float2bfloat16(v.w - __bfloat162float(h3));
    __nv_bfloat162* ph = (__nv_bfloat162*)hi;
    __nv_bfloat162* pl = (__nv_bfloat162*)lo;
    ph[2 * i]     = __nv_bfloat162(h0, h1);
    ph[2 * i + 1] = __nv_bfloat162(h2, h3);
    pl[2 * i]     = __nv_bfloat162(l0, l1);
    pl[2 * i + 1] = __nv_bfloat162(l2, l3);
}

// ---------------- PTX helpers (non-'a' features only) ------------------------
__device__ __forceinline__ uint32_t s2u(const void* p) {
    uint32_t a;
    asm("{ .reg .u64 t; cvta.to.shared.u64 t, %1; cvt.u32.u64 %0, t; }"
        : "=r"(a) : "l"(p));
    return a;
}

#define CP16(saddr, gptr) \
    asm volatile("cp.async.cg.shared.global [%0], [%1], 16;" \
                 :: "r"(saddr), "l"(gptr))
#define CP_COMMIT() asm volatile("cp.async.commit_group;" ::: "memory")
#define CP_WAIT0()  asm volatile("cp.async.wait_group 0;" ::: "memory")
#define CP_WAIT1()  asm volatile("cp.async.wait_group 1;" ::: "memory")

#define LDM_X4(R, addr) \
    asm volatile("ldmatrix.sync.aligned.m8n8.x4.shared.b16 {%0,%1,%2,%3}, [%4];" \
                 : "=r"((R)[0]), "=r"((R)[1]), "=r"((R)[2]), "=r"((R)[3]) \
                 : "r"(addr))
#define LDM_X4_T(R, addr) \
    asm volatile("ldmatrix.sync.aligned.m8n8.x4.trans.shared.b16 {%0,%1,%2,%3}, [%4];" \
                 : "=r"((R)[0]), "=r"((R)[1]), "=r"((R)[2]), "=r"((R)[3]) \
                 : "r"(addr))

#define MMA16816(C, A, B) \
    asm volatile("mma.sync.aligned.m16n8k16.row.col.f32.bf16.bf16.f32 " \
                 "{%0,%1,%2,%3}, {%4,%5,%6,%7}, {%8,%9}, {%0,%1,%2,%3};" \
                 : "+f"((C)[0]), "+f"((C)[1]), "+f"((C)[2]), "+f"((C)[3]) \
                 : "r"((A)[0]), "r"((A)[1]), "r"((A)[2]), "r"((A)[3]), \
                   "r"((B)[0]), "r"((B)[1]))

__device__ __forceinline__ uint32_t bf2(float lo, float hi) {
    uint32_t r;
    asm("cvt.rn.bf16x2.f32 %0, %1, %2;" : "=r"(r) : "f"(hi), "f"(lo));
    return r;
}
__device__ __forceinline__ float bfres(float x) {
    return x - __bfloat162float(__float2bfloat16(x));
}

// ---------------- mma.sync GEMM core -----------------------------------------
#define BKC   32
#define SAPD  40
#define TILE_ELE  (128 * SAPD)
#define STAGE_ELE (4 * TILE_ELE)
#define GEMM_SMEM_B (2 * STAGE_ELE * 2)   // 81920 bytes

__device__ __forceinline__ void gemm_load_stage(
    const __nv_bfloat16* __restrict__ Ahi, const __nv_bfloat16* __restrict__ Alo,
    const __nv_bfloat16* __restrict__ Bhi, const __nv_bfloat16* __restrict__ Blo,
    int K, int m0, int n0, int k0, uint32_t sdst, int tid) {
#pragma unroll
    for (int t = 0; t < 2; t++) {
        int idx = tid + t * 256;
        int row = idx >> 2;
        int c4  = idx & 3;
        uint32_t so = sdst + (uint32_t)(row * SAPD + c4 * 8) * 2;
        size_t aoff = (size_t)(m0 + row) * K + k0 + c4 * 8;
        size_t boff = (size_t)(n0 + row) * K + k0 + c4 * 8;
        CP16(so,                    Ahi + aoff);
        CP16(so + TILE_ELE * 2,     Alo + aoff);
        CP16(so + 2 * TILE_ELE * 2, Bhi + boff);
        CP16(so + 3 * TILE_ELE * 2, Blo + boff);
    }
    CP_COMMIT();
}

// Mainloop: computes acc[4][4][4] for warp tile 64x32 at (wm, wn).
__device__ __forceinline__ void gemm_mainloop(
    const __nv_bfloat16* __restrict__ Ahi, const __nv_bfloat16* __restrict__ Alo,
    const __nv_bfloat16* __restrict__ Bhi, const __nv_bfloat16* __restrict__ Blo,
    int K, int m0, int n0, uint32_t sbase, int tid, int lane, int wm, int wn,
    float acc[4][4][4]) {
    const int nchunk = K / BKC;
    gemm_load_stage(Ahi, Alo, Bhi, Blo, K, m0, n0, 0, sbase, tid);

    for (int c = 0; c < nchunk; c++) {
        if (c + 1 < nchunk) {
            gemm_load_stage(Ahi, Alo, Bhi, Blo, K, m0, n0, (c + 1) * BKC,
                            sbase + (uint32_t)(((c + 1) & 1) * STAGE_ELE) * 2, tid);
            CP_WAIT1();
        } else {
            CP_WAIT0();
        }
        __syncthreads();

        const uint32_t sa = sbase + (uint32_t)((c & 1) * STAGE_ELE) * 2;
        const uint32_t sb = sa + 2 * TILE_ELE * 2;
#pragma unroll
        for (int ks = 0; ks < 2; ks++) {
            uint32_t ah[4][4], al[4][4];
#pragma unroll
            for (int mi = 0; mi < 4; mi++) {
                int r  = wm + mi * 16 + (lane & 15);
                int cc = ks * 16 + ((lane >> 4) << 3);
                uint32_t ad = sa + (uint32_t)(r * SAPD + cc) * 2;
                LDM_X4(ah[mi], ad);
                LDM_X4(al[mi], ad + TILE_ELE * 2);
            }
            // B fragments via x4: quadrant mapping (same as attention kernel)
            uint32_t bh[2][4], bl[2][4];
#pragma unroll
            for (int np = 0; np < 2; np++) {
                int r  = wn + np * 16 + (lane & 7) + ((lane >> 4) & 1) * 8;
                int cc = ks * 16 + ((lane >> 3) & 1) * 8;
                uint32_t ad = sb + (uint32_t)(r * SAPD + cc) * 2;
                LDM_X4(bh[np], ad);
                LDM_X4(bl[np], ad + TILE_ELE * 2);
            }
#pragma unroll
            for (int mi = 0; mi < 4; mi++)
#pragma unroll
                for (int np = 0; np < 2; np++) {
                    MMA16816(acc[mi][2 * np],     ah[mi], &bh[np][0]);
                    MMA16816(acc[mi][2 * np],     ah[mi], &bl[np][0]);
                    MMA16816(acc[mi][2 * np],     al[mi], &bh[np][0]);
                    MMA16816(acc[mi][2 * np + 1], ah[mi], &bh[np][2]);
                    MMA16816(acc[mi][2 * np + 1], ah[mi], &bl[np][2]);
                    MMA16816(acc[mi][2 * np + 1], al[mi], &bh[np][2]);
                }
        }
        __syncthreads();
    }
}

// ---------------- fused QKV GEMM ---------------------------------------------
// grid.x: [0,16) Q tiles -> fp32 g_q; [16,20) K tiles -> fp32 g_k;
//         [20,24) V tiles -> bf16 hi/lo g_vah/g_val (no rope on V).
__global__ __launch_bounds__(256)
void gemm_qkv(const __nv_bfloat16* __restrict__ Xhi, const __nv_bfloat16* __restrict__ Xlo,
              const __nv_bfloat16* __restrict__ WQh, const __nv_bfloat16* __restrict__ WQl,
              const __nv_bfloat16* __restrict__ WKh, const __nv_bfloat16* __restrict__ WKl,
              const __nv_bfloat16* __restrict__ WVh, const __nv_bfloat16* __restrict__ WVl,
              float* __restrict__ Qout, float* __restrict__ Kout,
              __nv_bfloat16* __restrict__ Vhi, __nv_bfloat16* __restrict__ Vlo) {
    extern __shared__ __nv_bfloat16 smb[];
    const int tid  = threadIdx.x;
    const int lane = tid & 31;
    const int wid  = tid >> 5;
    const int wm   = (wid & 1) * 64;
    const int wn   = (wid >> 1) * 32;
    const int m0 = blockIdx.y * 128;
    const int bx = blockIdx.x;
    const uint32_t sbase = s2u(smb);

    const __nv_bfloat16 *Bh, *Bl;
    int n0, N, mode;   // mode 0 = fp32 out, 1 = bf16 hi/lo out
    float* Cf = 0;
    __nv_bfloat16 *Ch = 0, *Cl = 0;
    if (bx < 16)      { Bh = WQh; Bl = WQl; n0 = bx * 128;        N = NQ;  mode = 0; Cf = Qout; }
    else if (bx < 20) { Bh = WKh; Bl = WKl; n0 = (bx - 16) * 128; N = NKV; mode = 0; Cf = Kout; }
    else              { Bh = WVh; Bl = WVl; n0 = (bx - 20) * 128; N = NKV; mode = 1; Ch = Vhi; Cl = Vlo; }

    float acc[4][4][4];
#pragma unroll
    for (int mi = 0; mi < 4; mi++)
#pragma unroll
        for (int ni = 0; ni < 4; ni++)
#pragma unroll
            for (int r = 0; r < 4; r++) acc[mi][ni][r] = 0.f;

    gemm_mainloop(Xhi, Xlo, Bh, Bl, DD, m0, n0, sbase, tid, lane, wm, wn, acc);

    const int row0 = m0 + wm + (lane >> 2);
    const int col0 = n0 + wn + (lane & 3) * 2;
    if (mode == 0) {
#pragma unroll
        for (int mi = 0; mi < 4; mi++)
#pragma unroll
            for (int ni = 0; ni < 4; ni++) {
                float* p0 = Cf + (size_t)(row0 + mi * 16) * N + col0 + ni * 8;
                float* p1 = Cf + (size_t)(row0 + mi * 16 + 8) * N + col0 + ni * 8;
                *(float2*)p0 = make_float2(acc[mi][ni][0], acc[mi][ni][1]);
                *(float2*)p1 = make_float2(acc[mi][ni][2], acc[mi][ni][3]);
            }
    } else {
#pragma unroll
        for (int mi = 0; mi < 4; mi++)
#pragma unroll
            for (int ni = 0; ni < 4; ni++) {
                size_t o0 = (size_t)(row0 + mi * 16) * N + col0 + ni * 8;
                size_t o1 = (size_t)(row0 + mi * 16 + 8) * N + col0 + ni * 8;
                float a0 = acc[mi][ni][0], a1 = acc[mi][ni][1];
                float a2 = acc[mi][ni][2], a3 = acc[mi][ni][3];
                __nv_bfloat16 h0 = __float2bfloat16(a0), h1 = __float2bfloat16(a1);
                __nv_bfloat16 h2 = __float2bfloat16(a2), h3 = __float2bfloat16(a3);
                *(__nv_bfloat162*)(Ch + o0) = __nv_bfloat162(h0, h1);
                *(__nv_bfloat162*)(Ch + o1) = __nv_bfloat162(h2, h3);
                *(__nv_bfloat162*)(Cl + o0) = __nv_bfloat162(
                    __float2bfloat16(a0 - __bfloat162float(h0)),
                    __float2bfloat16(a1 - __bfloat162float(h1)));
                *(__nv_bfloat162*)(Cl + o1) = __nv_bfloat162(
                    __float2bfloat16(a2 - __bfloat162float(h2)),
                    __float2bfloat16(a3 - __bfloat162float(h3)));
            }
    }
}

// ---------------- O-projection GEMM (fp32 out) -------------------------------
__global__ __launch_bounds__(256)
void gemm_mma(const __nv_bfloat16* __restrict__ Ahi, const __nv_bfloat16* __restrict__ Alo,
              const __nv_bfloat16* __restrict__ Bhi, const __nv_bfloat16* __restrict__ Blo,
              float* __restrict__ C, int M, int N, int K) {
    extern __shared__ __nv_bfloat16 smb[];
    const int tid  = threadIdx.x;
    const int lane = tid & 31;
    const int wid  = tid >> 5;
    const int wm   = (wid & 1) * 64;
    const int wn   = (wid >> 1) * 32;
    const int m0 = blockIdx.y * 128;
    const int n0 = blockIdx.x * 128;
    const uint32_t sbase = s2u(smb);

    float acc[4][4][4];
#pragma unroll
    for (int mi = 0; mi < 4; mi++)
#pragma unroll
        for (int ni = 0; ni < 4; ni++)
#pragma unroll
            for (int r = 0; r < 4; r++) acc[mi][ni][r] = 0.f;

    gemm_mainloop(Ahi, Alo, Bhi, Blo, K, m0, n0, sbase, tid, lane, wm, wn, acc);

    const int row0 = m0 + wm + (lane >> 2);
    const int col0 = n0 + wn + (lane & 3) * 2;
#pragma unroll
    for (int mi = 0; mi < 4; mi++)
#pragma unroll
        for (int ni = 0; ni < 4; ni++) {
            float* p0 = C + (size_t)(row0 + mi * 16) * N + col0 + ni * 8;
            float* p1 = C + (size_t)(row0 + mi * 16 + 8) * N + col0 + ni * 8;
            *(float2*)p0 = make_float2(acc[mi][ni][0], acc[mi][ni][1]);
            *(float2*)p1 = make_float2(acc[mi][ni][2], acc[mi][ni][3]);
        }
}

// ---------------- Flash attention on mma.sync --------------------------------
#define AP   136
#define QT   (128 * AP)
#define KVT  (64 * AP)
#define STG  (4 * KVT)
#define ATT_SMEM_B ((2 * QT + 2 * STG) * 2)   // 208896 bytes

__device__ __forceinline__ void attn_load_kv(
    const __nv_bfloat16* __restrict__ Kh, const __nv_bfloat16* __restrict__ Kl,
    const __nv_bfloat16* __restrict__ Vh, const __nv_bfloat16* __restrict__ Vl,
    int b, int kvh, int j0, uint32_t base, int tid) {
#pragma unroll
    for (int t = 0; t < 4; t++) {
        int idx = tid + t * 256;
        int row = idx >> 4;
        int c   = idx & 15;
        uint32_t off = (uint32_t)(row * AP + c * 8) * 2;
        size_t g = ((size_t)(b * SS + j0 + row) * KVH + kvh) * DHD + c * 8;
        CP16(base + off,               Kh + g);
        CP16(base + KVT * 2 + off,     Kl + g);
        CP16(base + 2 * KVT * 2 + off, Vh + g);
        CP16(base + 3 * KVT * 2 + off, Vl + g);
    }
    CP_COMMIT();
}

__global__ __launch_bounds__(256, 1)
void attn_mma(const __nv_bfloat16* __restrict__ Qh, const __nv_bfloat16* __restrict__ Ql,
              const __nv_bfloat16* __restrict__ Kh, const __nv_bfloat16* __restrict__ Kl,
              const __nv_bfloat16* __restrict__ Vh, const __nv_bfloat16* __restrict__ Vl,
              __nv_bfloat16* __restrict__ Ohi, __nv_bfloat16* __restrict__ Olo) {
    extern __shared__ __nv_bfloat16 sa[];
    const int tid  = threadIdx.x;
    const int lane = tid & 31;
    const int wid  = tid >> 5;
    const int q0   = (gridDim.x - 1 - blockIdx.x) * 128;   // longest first
    const int h    = blockIdx.y;
    const int b    = blockIdx.z;
    const int kvh  = h >> 2;
    const uint32_t sb = s2u(sa);
    const uint32_t QHo = sb;
    const uint32_t QLo = sb + QT * 2;

    {
        const __nv_bfloat16* qgh = Qh + (((size_t)b * SS + q0) * HH + h) * DHD;
        const __nv_bfloat16* qgl = Ql + (((size_t)b * SS + q0) * HH + h) * DHD;
#pragma unroll
        for (int t = 0; t < 8; t++) {
            int idx = tid + t * 256;
            int row = idx >> 4;
            int c   = idx & 15;
            uint32_t off = (uint32_t)(row * AP + c * 8) * 2;
            size_t g = (size_t)row * (HH * DHD) + c * 8;
            CP16(QHo + off, qgh + g);
            CP16(QLo + off, qgl + g);
        }
        CP_COMMIT();
    }

    const int kv_end = min(q0 + 256, SS);
    const int nblk   = kv_end >> 6;
    const uint32_t stg0 = sb + 2 * QT * 2;

    attn_load_kv(Kh, Kl, Vh, Vl, b, kvh, 0, stg0, tid);

    float oacc[16][4];
#pragma unroll
    for (int df = 0; df < 16; df++)
#pragma unroll
        for (int r = 0; r < 4; r++) oacc[df][r] = 0.f;
    float m0r = -1e30f, m1r = -1e30f, l0r = 0.f, l1r = 0.f;

    const int r0 = wid * 16;

    for (int blk = 0; blk < nblk; blk++) {
        if (blk + 1 < nblk) {
            attn_load_kv(Kh, Kl, Vh, Vl, b, kvh, (blk + 1) * 64,
                         stg0 + (uint32_t)(((blk + 1) & 1) * STG) * 2, tid);
            CP_WAIT1();
        } else {
            CP_WAIT0();
        }
        __syncthreads();

        const uint32_t kb = stg0 + (uint32_t)((blk & 1) * STG) * 2;
        const uint32_t vb = kb + 2 * KVT * 2;

        float sacc[8][4];
#pragma unroll
        for (int nf = 0; nf < 8; nf++)
#pragma unroll
            for (int r = 0; r < 4; r++) sacc[nf][r] = 0.f;

#pragma unroll
        for (int ks = 0; ks < 8; ks++) {
            uint32_t ah[4], al[4];
            uint32_t qa = QHo + (uint32_t)((r0 + (lane & 15)) * AP +
                                           ks * 16 + ((lane >> 4) << 3)) * 2;
            LDM_X4(ah, qa);
            LDM_X4(al, qa + QT * 2);
#pragma unroll
            for (int np = 0; np < 4; np++) {
                uint32_t bh[4], bl[4];
                uint32_t ba = kb + (uint32_t)((np * 16 + (lane & 7) + ((lane >> 4) & 1) * 8) * AP +
                                              ks * 16 + ((lane >> 3) & 1) * 8) * 2;
                LDM_X4(bh, ba);
                LDM_X4(bl, ba + KVT * 2);
                MMA16816(sacc[2 * np],     ah, &bh[0]);
                MMA16816(sacc[2 * np],     ah, &bl[0]);
                MMA16816(sacc[2 * np],     al, &bh[0]);
                MMA16816(sacc[2 * np + 1], ah, &bh[2]);
                MMA16816(sacc[2 * np + 1], ah, &bl[2]);
                MMA16816(sacc[2 * np + 1], al, &bh[2]);
            }
        }

        const int j0 = blk * 64;
        if (j0 + 63 > q0 + WIN) {
            const int rq = q0 + r0 + (lane >> 2);
#pragma unroll
            for (int nf = 0; nf < 8; nf++) {
#pragma unroll
                for (int e = 0; e < 2; e++) {
                    int k = j0 + nf * 8 + (lane & 3) * 2 + e;
                    if (k > rq + WIN)     sacc[nf][e]     = -1e30f;
                    if (k > rq + 8 + WIN) sacc[nf][2 + e] = -1e30f;
                }
            }
        }

        float mx0 = -1e30f, mx1 = -1e30f;
#pragma unroll
        for (int nf = 0; nf < 8; nf++) {
            mx0 = fmaxf(mx0, fmaxf(sacc[nf][0], sacc[nf][1]));
            mx1 = fmaxf(mx1, fmaxf(sacc[nf][2], sacc[nf][3]));
        }
        mx0 = fmaxf(mx0, __shfl_xor_sync(0xffffffffu, mx0, 1));
        mx0 = fmaxf(mx0, __shfl_xor_sync(0xffffffffu, mx0, 2));
        mx1 = fmaxf(mx1, __shfl_xor_sync(0xffffffffu, mx1, 1));
        mx1 = fmaxf(mx1, __shfl_xor_sync(0xffffffffu, mx1, 2));
        float mn0 = fmaxf(m0r, mx0), mn1 = fmaxf(m1r, mx1);
        float a0 = __expf(m0r - mn0), a1 = __expf(m1r - mn1);
        m0r = mn0; m1r = mn1;
        float s0 = 0.f, s1 = 0.f;
#pragma unroll
        for (int nf = 0; nf < 8; nf++) {
            sacc[nf][0] = __expf(sacc[nf][0] - mn0);
            sacc[nf][1] = __expf(sacc[nf][1] - mn0);
            sacc[nf][2] = __expf(sacc[nf][2] - mn1);
            sacc[nf][3] = __expf(sacc[nf][3] - mn1);
            s0 += sacc[nf][0] + sacc[nf][1];
            s1 += sacc[nf][2] + sacc[nf][3];
        }
        s0 += __shfl_xor_sync(0xffffffffu, s0, 1);
        s0 += __shfl_xor_sync(0xffffffffu, s0, 2);
        s1 += __shfl_xor_sync(0xffffffffu, s1, 1);
        s1 += __shfl_xor_sync(0xffffffffu, s1, 2);
        l0r = l0r * a0 + s0;
        l1r = l1r * a1 + s1;
#pragma unroll
        for (int df = 0; df < 16; df++) {
            oacc[df][0] *= a0; oacc[df][1] *= a0;
            oacc[df][2] *= a1; oacc[df][3] *= a1;
        }

#pragma unroll
        for (int kk = 0; kk < 4; kk++) {
            const float* f0 = sacc[2 * kk];
            const float* f1 = sacc[2 * kk + 1];
            uint32_t ph[4], pl[4];
            ph[0] = bf2(f0[0], f0[1]); ph[1] = bf2(f0[2], f0[3]);
            ph[2] = bf2(f1[0], f1[1]); ph[3] = bf2(f1[2], f1[3]);
            pl[0] = bf2(bfres(f0[0]), bfres(f0[1]));
            pl[1] = bf2(bfres(f0[2]), bfres(f0[3]));
            pl[2] = bf2(bfres(f1[0]), bfres(f1[1]));
            pl[3] = bf2(bfres(f1[2]), bfres(f1[3]));
#pragma unroll
            for (int dp = 0; dp < 8; dp++) {
                uint32_t bvh[4], bvl[4];
                uint32_t va = vb + (uint32_t)((kk * 16 + (lane & 15)) * AP +
                                              dp * 16 + ((lane >> 4) << 3)) * 2;
                LDM_X4_T(bvh, va);
                LDM_X4_T(bvl, va + KVT * 2);
                MMA16816(oacc[2 * dp],     ph, &bvh[0]);
                MMA16816(oacc[2 * dp],     ph, &bvl[0]);
                MMA16816(oacc[2 * dp],     pl, &bvh[0]);
                MMA16816(oacc[2 * dp + 1], ph, &bvh[2]);
                MMA16816(oacc[2 * dp + 1], ph, &bvl[2]);
                MMA16816(oacc[2 * dp + 1], pl, &bvh[2]);
            }
        }
        __syncthreads();
    }

    // ---- epilogue: write hi/lo bf16 directly (feeds O-projection) ----
    const float inv0 = 1.0f / l0r;
    const float inv1 = 1.0f / l1r;
    const int rq = q0 + r0 + (lane >> 2);
    size_t base0 = (((size_t)b * SS + rq) * HH + h) * DHD;
    size_t base1 = base0 + (size_t)8 * HH * DHD;
#pragma unroll
    for (int df = 0; df < 16; df++) {
        int col = df * 8 + (lane & 3) * 2;
        float v0 = oacc[df][0] * inv0, v1 = oacc[df][1] * inv0;
        float v2 = oacc[df][2] * inv1, v3 = oacc[df][3] * inv1;
        __nv_bfloat16 h0 = __float2bfloat16(v0), h1 = __float2bfloat16(v1);
        __nv_bfloat16 h2 = __float2bfloat16(v2), h3 = __float2bfloat16(v3);
        *(__nv_bfloat162*)(Ohi + base0 + col) = __nv_bfloat162(h0, h1);
        *(__nv_bfloat162*)(Ohi + base1 + col) = __nv_bfloat162(h2, h3);
        *(__nv_bfloat162*)(Olo + base0 + col) = __nv_bfloat162(
            __float2bfloat16(v0 - __bfloat162float(h0)),
            __float2bfloat16(v1 - __bfloat162float(h1)));
        *(__nv_bfloat162*)(Olo + base1 + col) = __nv_bfloat162(
            __float2bfloat16(v2 - __bfloat162float(h2)),
            __float2bfloat16(v3 - __bfloat162float(h3)));
    }
}

// ---------------- launch ----------------------------------------------------
extern "C" void kernel_launch(void* const* d_in, const int* in_sizes, int n_in,
                              void* d_out, int out_size) {
    const float* x  = (const float*)d_in[0];
    const float* Wq = (const float*)d_in[1];
    const float* Wk = (const float*)d_in[2];
    const float* Wv = (const float*)d_in[3];
    const float* Wo = (const float*)d_in[4];
    float* out = (float*)d_out;

    void *pq, *pk;
    void *pxh, *pxl, *pqh, *pql, *pkh, *pkl, *pvh, *pvl, *poh, *pol, *pah, *pal;
    void *aqh, *aql, *akh, *akl, *avh, *avl;
    cudaGetSymbolAddress(&pq, g_q);
    cudaGetSymbolAddress(&pk, g_k);
    cudaGetSymbolAddress(&pxh, g_xhi);  cudaGetSymbolAddress(&pxl, g_xlo);
    cudaGetSymbolAddress(&pqh, g_wqhi); cudaGetSymbolAddress(&pql, g_wqlo);
    cudaGetSymbolAddress(&pkh, g_wkhi); cudaGetSymbolAddress(&pkl, g_wklo);
    cudaGetSymbolAddress(&pvh, g_wvhi); cudaGetSymbolAddress(&pvl, g_wvlo);
    cudaGetSymbolAddress(&poh, g_wohi); cudaGetSymbolAddress(&pol, g_wolo);
    cudaGetSymbolAddress(&pah, g_ahi);  cudaGetSymbolAddress(&pal, g_alo);
    cudaGetSymbolAddress(&aqh, g_qah);  cudaGetSymbolAddress(&aql, g_qal);
    cudaGetSymbolAddress(&akh, g_kah);  cudaGetSymbolAddress(&akl, g_kal);
    cudaGetSymbolAddress(&avh, g_vah);  cudaGetSymbolAddress(&avl, g_val);
    float* Qb = (float*)pq;
    float* Kb = (float*)pk;

    cudaFuncSetAttribute(gemm_qkv,
                         cudaFuncAttributeMaxDynamicSharedMemorySize, GEMM_SMEM_B);
    cudaFuncSetAttribute(gemm_mma,
                         cudaFuncAttributeMaxDynamicSharedMemorySize, GEMM_SMEM_B);
    cudaFuncSetAttribute(attn_mma,
                         cudaFuncAttributeMaxDynamicSharedMemorySize, ATT_SMEM_B);

    // RoPE tables
    rope_tables_kernel<<<(SS * 64 + 255) / 256, 256>>>();

    // hi/lo splits of inputs and weights
    split_kernel<<<(MTOK * DD / 4 + 255) / 256, 256>>>(
        x, (__nv_bfloat16*)pxh, (__nv_bfloat16*)pxl, MTOK * DD / 4);
    split_kernel<<<(NQ * DD / 4 + 255) / 256, 256>>>(
        Wq, (__nv_bfloat16*)pqh, (__nv_bfloat16*)pql, NQ * DD / 4);
    split_kernel<<<(NKV * DD / 4 + 255) / 256, 256>>>(
        Wk, (__nv_bfloat16*)pkh, (__nv_bfloat16*)pkl, NKV * DD / 4);
    split_kernel<<<(NKV * DD / 4 + 255) / 256, 256>>>(
        Wv, (__nv_bfloat16*)pvh, (__nv_bfloat16*)pvl, NKV * DD / 4);
    split_kernel<<<(DD * NQ / 4 + 255) / 256, 256>>>(
        Wo, (__nv_bfloat16*)poh, (__nv_bfloat16*)pol, DD * NQ / 4);

    // Fused Q/K/V projections (V epilogue emits bf16 hi/lo directly)
    gemm_qkv<<<dim3(24, MTOK / 128), 256, GEMM_SMEM_B>>>(
        (const __nv_bfloat16*)pxh, (const __nv_bfloat16*)pxl,
        (const __nv_bfloat16*)pqh, (const __nv_bfloat16*)pql,
        (const __nv_bfloat16*)pkh, (const __nv_bfloat16*)pkl,
        (const __nv_bfloat16*)pvh, (const __nv_bfloat16*)pvl,
        Qb, Kb, (__nv_bfloat16*)avh, (__nv_bfloat16*)avl);

    // Fused RoPE + split (Q gets softmax scale folded in)
    const float scale = 0.08838834764831845f;   // 1/sqrt(128)
    rope_split_kernel<<<(MTOK * HH * 64 + 255) / 256, 256>>>(
        Qb, (__nv_bfloat16*)aqh, (__nv_bfloat16*)aql, HH, scale);
    rope_split_kernel<<<(MTOK * KVH * 64 + 255) / 256, 256>>>(
        Kb, (__nv_bfloat16*)akh, (__nv_bfloat16*)akl, KVH, 1.0f);

    // Attention on tensor cores -> bf16 hi/lo output
    attn_mma<<<dim3(SS / 128, HH, BB), 256, ATT_SMEM_B>>>(
        (const __nv_bfloat16*)aqh, (const __nv_bfloat16*)aql,
        (const __nv_bfloat16*)akh, (const __nv_bfloat16*)akl,
        (const __nv_bfloat16*)avh, (const __nv_bfloat16*)avl,
        (__nv_bfloat16*)pah, (__nv_bfloat16*)pal);

    // O projection
    gemm_mma<<<dim3(DD / 128, MTOK / 128), 256, GEMM_SMEM_B>>>(
        (const __nv_bfloat16*)pah, (const __nv_bfloat16*)pal,
        (const __nv_bfloat16*)poh, (const __nv_bfloat16*)pol,
        out, MTOK, DD, NQ);
}

// round 8
// speedup vs baseline: 2.9663x; 1.0021x over previous
#include <cuda_runtime.h>
#include <cuda_bf16.h>
#include <math.h>
#include <stdint.h>

// Problem constants
#define BB    2
#define SS    2048
#define DD    2048
#define HH    16
#define KVH   4
#define DHD   128
#define WIN   128
#define MTOK  (BB*SS)          // 4096 tokens
#define NQ    (HH*DHD)         // 2048
#define NKV   (KVH*DHD)        // 512

// ---------------- scratch (device globals; no allocation allowed) ----------
__device__ float g_cos[SS * 64];
__device__ float g_sin[SS * 64];
// hi/lo bf16 splits (GEMM operands)
__device__ __align__(256) __nv_bfloat16 g_xhi[MTOK * DD],  g_xlo[MTOK * DD];
__device__ __align__(256) __nv_bfloat16 g_wqhi[NQ * DD],   g_wqlo[NQ * DD];
__device__ __align__(256) __nv_bfloat16 g_wkhi[NKV * DD],  g_wklo[NKV * DD];
__device__ __align__(256) __nv_bfloat16 g_wvhi[NKV * DD],  g_wvlo[NKV * DD];
__device__ __align__(256) __nv_bfloat16 g_wohi[DD * NQ],   g_wolo[DD * NQ];
__device__ __align__(256) __nv_bfloat16 g_ahi[MTOK * NQ],  g_alo[MTOK * NQ];
// attention operands (post-RoPE hi/lo)
__device__ __align__(256) __nv_bfloat16 g_qah[MTOK * NQ],  g_qal[MTOK * NQ];
__device__ __align__(256) __nv_bfloat16 g_kah[MTOK * NKV], g_kal[MTOK * NKV];
__device__ __align__(256) __nv_bfloat16 g_vah[MTOK * NKV], g_val[MTOK * NKV];

// ---------------- RoPE tables ----------------------------------------------
__global__ void rope_tables_kernel() {
    int idx = blockIdx.x * blockDim.x + threadIdx.x;
    if (idx >= SS * 64) return;
    int s = idx >> 6;
    int j = idx & 63;
    double freq = exp(-((double)(2 * j) / 128.0) * 9.210340371976184); // ln(10000)
    double a = (double)s * freq;
    g_cos[idx] = (float)cos(a);
    g_sin[idx] = (float)sin(a);
}

// ---------------- merged hi/lo bf16 split (5 tensors, one launch) -----------
#define X4B   8192      // MTOK*DD/4 / 256
#define WQ4B  4096
#define WK4B  1024
#define WV4B  1024
#define WO4B  4096

__device__ __forceinline__ void split_one(const float* __restrict__ src,
                                          __nv_bfloat16* __restrict__ hi,
                                          __nv_bfloat16* __restrict__ lo, int i) {
    float4 v = ((const float4*)src)[i];
    __nv_bfloat16 h0 = __float2bfloat16(v.x);
    __nv_bfloat16 h1 = __float2bfloat16(v.y);
    __nv_bfloat16 h2 = __float2bfloat16(v.z);
    __nv_bfloat16 h3 = __float2bfloat16(v.w);
    __nv_bfloat162* ph = (__nv_bfloat162*)hi;
    __nv_bfloat162* pl = (__nv_bfloat162*)lo;
    ph[2 * i]     = __nv_bfloat162(h0, h1);
    ph[2 * i + 1] = __nv_bfloat162(h2, h3);
    pl[2 * i]     = __nv_bfloat162(__float2bfloat16(v.x - __bfloat162float(h0)),
                                   __float2bfloat16(v.y - __bfloat162float(h1)));
    pl[2 * i + 1] = __nv_bfloat162(__float2bfloat16(v.z - __bfloat162float(h2)),
                                   __float2bfloat16(v.w - __bfloat162float(h3)));
}

__global__ void split_all_kernel(
    const float* __restrict__ x,  __nv_bfloat16* xh, __nv_bfloat16* xl,
    const float* __restrict__ wq, __nv_bfloat16* qh, __nv_bfloat16* ql,
    const float* __restrict__ wk, __nv_bfloat16* kh, __nv_bfloat16* kl,
    const float* __restrict__ wv, __nv_bfloat16* vh, __nv_bfloat16* vl,
    const float* __restrict__ wo, __nv_bfloat16* oh, __nv_bfloat16* ol) {
    int bx = blockIdx.x;
    int t  = threadIdx.x;
    if (bx < X4B) {
        split_one(x, xh, xl, bx * 256 + t);
    } else if (bx < X4B + WQ4B) {
        split_one(wq, qh, ql, (bx - X4B) * 256 + t);
    } else if (bx < X4B + WQ4B + WK4B) {
        split_one(wk, kh, kl, (bx - X4B - WQ4B) * 256 + t);
    } else if (bx < X4B + WQ4B + WK4B + WV4B) {
        split_one(wv, vh, vl, (bx - X4B - WQ4B - WK4B) * 256 + t);
    } else {
        split_one(wo, oh, ol, (bx - X4B - WQ4B - WK4B - WV4B) * 256 + t);
    }
}

// ---------------- PTX helpers (non-'a' features only) ------------------------
__device__ __forceinline__ uint32_t s2u(const void* p) {
    uint32_t a;
    asm("{ .reg .u64 t; cvta.to.shared.u64 t, %1; cvt.u32.u64 %0, t; }"
        : "=r"(a) : "l"(p));
    return a;
}

#define CP16(saddr, gptr) \
    asm volatile("cp.async.cg.shared.global [%0], [%1], 16;" \
                 :: "r"(saddr), "l"(gptr))
#define CP_COMMIT() asm volatile("cp.async.commit_group;" ::: "memory")
#define CP_WAIT0()  asm volatile("cp.async.wait_group 0;" ::: "memory")
#define CP_WAIT1()  asm volatile("cp.async.wait_group 1;" ::: "memory")

#define LDM_X4(R, addr) \
    asm volatile("ldmatrix.sync.aligned.m8n8.x4.shared.b16 {%0,%1,%2,%3}, [%4];" \
                 : "=r"((R)[0]), "=r"((R)[1]), "=r"((R)[2]), "=r"((R)[3]) \
                 : "r"(addr))
#define LDM_X4_T(R, addr) \
    asm volatile("ldmatrix.sync.aligned.m8n8.x4.trans.shared.b16 {%0,%1,%2,%3}, [%4];" \
                 : "=r"((R)[0]), "=r"((R)[1]), "=r"((R)[2]), "=r"((R)[3]) \
                 : "r"(addr))

#define MMA16816(C, A, B) \
    asm volatile("mma.sync.aligned.m16n8k16.row.col.f32.bf16.bf16.f32 " \
                 "{%0,%1,%2,%3}, {%4,%5,%6,%7}, {%8,%9}, {%0,%1,%2,%3};" \
                 : "+f"((C)[0]), "+f"((C)[1]), "+f"((C)[2]), "+f"((C)[3]) \
                 : "r"((A)[0]), "r"((A)[1]), "r"((A)[2]), "r"((A)[3]), \
                   "r"((B)[0]), "r"((B)[1]))

__device__ __forceinline__ uint32_t bf2(float lo, float hi) {
    uint32_t r;
    asm("cvt.rn.bf16x2.f32 %0, %1, %2;" : "=r"(r) : "f"(hi), "f"(lo));
    return r;
}
__device__ __forceinline__ float bfres(float x) {
    return x - __bfloat162float(__float2bfloat16(x));
}

// ---------------- mma.sync GEMM core -----------------------------------------
#define BKC   32
#define SAPD  40
#define TILE_ELE  (128 * SAPD)
#define STAGE_ELE (4 * TILE_ELE)
#define GEMM_SMEM_B (2 * STAGE_ELE * 2)   // 81920 bytes (also fits 64KB fp32 stage)

__device__ __forceinline__ void gemm_load_stage(
    const __nv_bfloat16* __restrict__ Ahi, const __nv_bfloat16* __restrict__ Alo,
    const __nv_bfloat16* __restrict__ Bhi, const __nv_bfloat16* __restrict__ Blo,
    int K, int m0, int n0, int k0, uint32_t sdst, int tid) {
#pragma unroll
    for (int t = 0; t < 2; t++) {
        int idx = tid + t * 256;
        int row = idx >> 2;
        int c4  = idx & 3;
        uint32_t so = sdst + (uint32_t)(row * SAPD + c4 * 8) * 2;
        size_t aoff = (size_t)(m0 + row) * K + k0 + c4 * 8;
        size_t boff = (size_t)(n0 + row) * K + k0 + c4 * 8;
        CP16(so,                    Ahi + aoff);
        CP16(so + TILE_ELE * 2,     Alo + aoff);
        CP16(so + 2 * TILE_ELE * 2, Bhi + boff);
        CP16(so + 3 * TILE_ELE * 2, Blo + boff);
    }
    CP_COMMIT();
}

__device__ __forceinline__ void gemm_mainloop(
    const __nv_bfloat16* __restrict__ Ahi, const __nv_bfloat16* __restrict__ Alo,
    const __nv_bfloat16* __restrict__ Bhi, const __nv_bfloat16* __restrict__ Blo,
    int K, int m0, int n0, uint32_t sbase, int tid, int lane, int wm, int wn,
    float acc[4][4][4]) {
    const int nchunk = K / BKC;
    gemm_load_stage(Ahi, Alo, Bhi, Blo, K, m0, n0, 0, sbase, tid);

    for (int c = 0; c < nchunk; c++) {
        if (c + 1 < nchunk) {
            gemm_load_stage(Ahi, Alo, Bhi, Blo, K, m0, n0, (c + 1) * BKC,
                            sbase + (uint32_t)(((c + 1) & 1) * STAGE_ELE) * 2, tid);
            CP_WAIT1();
        } else {
            CP_WAIT0();
        }
        __syncthreads();

        const uint32_t sa = sbase + (uint32_t)((c & 1) * STAGE_ELE) * 2;
        const uint32_t sb = sa + 2 * TILE_ELE * 2;
#pragma unroll
        for (int ks = 0; ks < 2; ks++) {
            uint32_t ah[4][4], al[4][4];
#pragma unroll
            for (int mi = 0; mi < 4; mi++) {
                int r  = wm + mi * 16 + (lane & 15);
                int cc = ks * 16 + ((lane >> 4) << 3);
                uint32_t ad = sa + (uint32_t)(r * SAPD + cc) * 2;
                LDM_X4(ah[mi], ad);
                LDM_X4(al[mi], ad + TILE_ELE * 2);
            }
            uint32_t bh[2][4], bl[2][4];
#pragma unroll
            for (int np = 0; np < 2; np++) {
                int r  = wn + np * 16 + (lane & 7) + ((lane >> 4) & 1) * 8;
                int cc = ks * 16 + ((lane >> 3) & 1) * 8;
                uint32_t ad = sb + (uint32_t)(r * SAPD + cc) * 2;
                LDM_X4(bh[np], ad);
                LDM_X4(bl[np], ad + TILE_ELE * 2);
            }
#pragma unroll
            for (int mi = 0; mi < 4; mi++)
#pragma unroll
                for (int np = 0; np < 2; np++) {
                    MMA16816(acc[mi][2 * np],     ah[mi], &bh[np][0]);
                    MMA16816(acc[mi][2 * np],     ah[mi], &bl[np][0]);
                    MMA16816(acc[mi][2 * np],     al[mi], &bh[np][0]);
                    MMA16816(acc[mi][2 * np + 1], ah[mi], &bh[np][2]);
                    MMA16816(acc[mi][2 * np + 1], ah[mi], &bl[np][2]);
                    MMA16816(acc[mi][2 * np + 1], al[mi], &bh[np][2]);
                }
        }
        __syncthreads();
    }
}

// ---------------- fused QKV GEMM with RoPE+split epilogue --------------------
// grid.x: [0,16) Q heads -> rope+scale -> g_qah/g_qal
//         [16,20) K heads -> rope       -> g_kah/g_kal
//         [20,24) V tiles  -> direct hi/lo -> g_vah/g_val
__global__ __launch_bounds__(256)
void gemm_qkv(const __nv_bfloat16* __restrict__ Xhi, const __nv_bfloat16* __restrict__ Xlo,
              const __nv_bfloat16* __restrict__ WQh, const __nv_bfloat16* __restrict__ WQl,
              const __nv_bfloat16* __restrict__ WKh, const __nv_bfloat16* __restrict__ WKl,
              const __nv_bfloat16* __restrict__ WVh, const __nv_bfloat16* __restrict__ WVl,
              __nv_bfloat16* __restrict__ Qhi, __nv_bfloat16* __restrict__ Qlo,
              __nv_bfloat16* __restrict__ Khi, __nv_bfloat16* __restrict__ Klo,
              __nv_bfloat16* __restrict__ Vhi, __nv_bfloat16* __restrict__ Vlo) {
    extern __shared__ __nv_bfloat16 smb[];
    const int tid  = threadIdx.x;
    const int lane = tid & 31;
    const int wid  = tid >> 5;
    const int wm   = (wid & 1) * 64;
    const int wn   = (wid >> 1) * 32;
    const int m0 = blockIdx.y * 128;
    const int bx = blockIdx.x;
    const uint32_t sbase = s2u(smb);

    const __nv_bfloat16 *Bh, *Bl;
    int n0, mode, head, nheads;
    __nv_bfloat16 *Oh, *Ol;
    float scl;
    if (bx < 16) {        // Q: rope + softmax scale
        Bh = WQh; Bl = WQl; n0 = bx * 128;
        mode = 0; head = bx; nheads = HH; Oh = Qhi; Ol = Qlo;
        scl = 0.08838834764831845f;
    } else if (bx < 20) { // K: rope
        Bh = WKh; Bl = WKl; n0 = (bx - 16) * 128;
        mode = 0; head = bx - 16; nheads = KVH; Oh = Khi; Ol = Klo;
        scl = 1.0f;
    } else {              // V: direct hi/lo
        Bh = WVh; Bl = WVl; n0 = (bx - 20) * 128;
        mode = 1; head = bx - 20; nheads = KVH; Oh = Vhi; Ol = Vlo;
        scl = 1.0f;
    }

    float acc[4][4][4];
#pragma unroll
    for (int mi = 0; mi < 4; mi++)
#pragma unroll
        for (int ni = 0; ni < 4; ni++)
#pragma unroll
            for (int r = 0; r < 4; r++) acc[mi][ni][r] = 0.f;

    gemm_mainloop(Xhi, Xlo, Bh, Bl, DD, m0, n0, sbase, tid, lane, wm, wn, acc);

    if (mode == 1) {
        // V: direct bf16 hi/lo writes
        const int row0 = wm + (lane >> 2);
        const int col0 = wn + (lane & 3) * 2;
#pragma unroll
        for (int mi = 0; mi < 4; mi++)
#pragma unroll
            for (int ni = 0; ni < 4; ni++) {
                size_t o0 = (size_t)(m0 + row0 + mi * 16) * NKV + head * DHD + col0 + ni * 8;
                size_t o1 = o0 + (size_t)8 * NKV;
                float a0 = acc[mi][ni][0], a1 = acc[mi][ni][1];
                float a2 = acc[mi][ni][2], a3 = acc[mi][ni][3];
                __nv_bfloat16 h0 = __float2bfloat16(a0), h1 = __float2bfloat16(a1);
                __nv_bfloat16 h2 = __float2bfloat16(a2), h3 = __float2bfloat16(a3);
                *(__nv_bfloat162*)(Oh + o0) = __nv_bfloat162(h0, h1);
                *(__nv_bfloat162*)(Oh + o1) = __nv_bfloat162(h2, h3);
                *(__nv_bfloat162*)(Ol + o0) = __nv_bfloat162(
                    __float2bfloat16(a0 - __bfloat162float(h0)),
                    __float2bfloat16(a1 - __bfloat162float(h1)));
                *(__nv_bfloat162*)(Ol + o1) = __nv_bfloat162(
                    __float2bfloat16(a2 - __bfloat162float(h2)),
                    __float2bfloat16(a3 - __bfloat162float(h3)));
            }
        return;
    }

    // ---- Q/K: stage fp32 tile in smem, apply RoPE, emit hi/lo bf16 ----
    float* stage = (float*)smb;   // 128x128 fp32 = 64KB (fits in 80KB pipeline buf)
    {
        const int rl = wm + (lane >> 2);
        const int cl = wn + (lane & 3) * 2;
#pragma unroll
        for (int mi = 0; mi < 4; mi++)
#pragma unroll
            for (int ni = 0; ni < 4; ni++) {
                stage[(rl + mi * 16) * 128 + cl + ni * 8]     = acc[mi][ni][0];
                stage[(rl + mi * 16) * 128 + cl + ni * 8 + 1] = acc[mi][ni][1];
                stage[(rl + mi * 16 + 8) * 128 + cl + ni * 8]     = acc[mi][ni][2];
                stage[(rl + mi * 16 + 8) * 128 + cl + ni * 8 + 1] = acc[mi][ni][3];
            }
    }
    __syncthreads();

    // warp w handles rows it*8 + w; lane l handles dims (2l, 2l+1) paired with +64
#pragma unroll 2
    for (int it = 0; it < 16; it++) {
        int row = it * 8 + wid;
        int pos = (m0 + row) & (SS - 1);
        float x0a = stage[row * 128 + 2 * lane];
        float x0b = stage[row * 128 + 2 * lane + 1];
        float x1a = stage[row * 128 + 2 * lane + 64];
        float x1b = stage[row * 128 + 2 * lane + 65];
        float c0 = g_cos[pos * 64 + lane],      s0 = g_sin[pos * 64 + lane];
        float c1 = g_cos[pos * 64 + 32 + lane], s1 = g_sin[pos * 64 + 32 + lane];
        float y0a = (x0a * c0 - x1a * s0) * scl;
        float y0b = (x0b * c0 - x1b * s0) * scl;
        float y1a = (x1a * c1 + x0a * s1) * scl;
        float y1b = (x1b * c1 + x0b * s1) * scl;
        __nv_bfloat16 h0a = __float2bfloat16(y0a), h0b = __float2bfloat16(y0b);
        __nv_bfloat16 h1a = __float2bfloat16(y1a), h1b = __float2bfloat16(y1b);
        size_t gb = (size_t)(m0 + row) * (nheads * DHD) + head * DHD;
        *(__nv_bfloat162*)(Oh + gb + 2 * lane)      = __nv_bfloat162(h0a, h0b);
        *(__nv_bfloat162*)(Oh + gb + 2 * lane + 64) = __nv_bfloat162(h1a, h1b);
        *(__nv_bfloat162*)(Ol + gb + 2 * lane) = __nv_bfloat162(
            __float2bfloat16(y0a - __bfloat162float(h0a)),
            __float2bfloat16(y0b - __bfloat162float(h0b)));
        *(__nv_bfloat162*)(Ol + gb + 2 * lane + 64) = __nv_bfloat162(
            __float2bfloat16(y1a - __bfloat162float(h1a)),
            __float2bfloat16(y1b - __bfloat162float(h1b)));
    }
}

// ---------------- O-projection GEMM (fp32 out) -------------------------------
__global__ __launch_bounds__(256)
void gemm_mma(const __nv_bfloat16* __restrict__ Ahi, const __nv_bfloat16* __restrict__ Alo,
              const __nv_bfloat16* __restrict__ Bhi, const __nv_bfloat16* __restrict__ Blo,
              float* __restrict__ C, int M, int N, int K) {
    extern __shared__ __nv_bfloat16 smb[];
    const int tid  = threadIdx.x;
    const int lane = tid & 31;
    const int wid  = tid >> 5;
    const int wm   = (wid & 1) * 64;
    const int wn   = (wid >> 1) * 32;
    const int m0 = blockIdx.y * 128;
    const int n0 = blockIdx.x * 128;
    const uint32_t sbase = s2u(smb);

    float acc[4][4][4];
#pragma unroll
    for (int mi = 0; mi < 4; mi++)
#pragma unroll
        for (int ni = 0; ni < 4; ni++)
#pragma unroll
            for (int r = 0; r < 4; r++) acc[mi][ni][r] = 0.f;

    gemm_mainloop(Ahi, Alo, Bhi, Blo, K, m0, n0, sbase, tid, lane, wm, wn, acc);

    const int row0 = m0 + wm + (lane >> 2);
    const int col0 = n0 + wn + (lane & 3) * 2;
#pragma unroll
    for (int mi = 0; mi < 4; mi++)
#pragma unroll
        for (int ni = 0; ni < 4; ni++) {
            float* p0 = C + (size_t)(row0 + mi * 16) * N + col0 + ni * 8;
            float* p1 = C + (size_t)(row0 + mi * 16 + 8) * N + col0 + ni * 8;
            *(float2*)p0 = make_float2(acc[mi][ni][0], acc[mi][ni][1]);
            *(float2*)p1 = make_float2(acc[mi][ni][2], acc[mi][ni][3]);
        }
}

// ---------------- Flash attention on mma.sync --------------------------------
#define AP   136
#define QT   (128 * AP)
#define KVT  (64 * AP)
#define STG  (4 * KVT)
#define ATT_SMEM_B ((2 * QT + 2 * STG) * 2)   // 208896 bytes

__device__ __forceinline__ void attn_load_kv(
    const __nv_bfloat16* __restrict__ Kh, const __nv_bfloat16* __restrict__ Kl,
    const __nv_bfloat16* __restrict__ Vh, const __nv_bfloat16* __restrict__ Vl,
    int b, int kvh, int j0, uint32_t base, int tid) {
#pragma unroll
    for (int t = 0; t < 4; t++) {
        int idx = tid + t * 256;
        int row = idx >> 4;
        int c   = idx & 15;
        uint32_t off = (uint32_t)(row * AP + c * 8) * 2;
        size_t g = ((size_t)(b * SS + j0 + row) * KVH + kvh) * DHD + c * 8;
        CP16(base + off,               Kh + g);
        CP16(base + KVT * 2 + off,     Kl + g);
        CP16(base + 2 * KVT * 2 + off, Vh + g);
        CP16(base + 3 * KVT * 2 + off, Vl + g);
    }
    CP_COMMIT();
}

__global__ __launch_bounds__(256, 1)
void attn_mma(const __nv_bfloat16* __restrict__ Qh, const __nv_bfloat16* __restrict__ Ql,
              const __nv_bfloat16* __restrict__ Kh, const __nv_bfloat16* __restrict__ Kl,
              const __nv_bfloat16* __restrict__ Vh, const __nv_bfloat16* __restrict__ Vl,
              __nv_bfloat16* __restrict__ Ohi, __nv_bfloat16* __restrict__ Olo) {
    extern __shared__ __nv_bfloat16 sa[];
    const int tid  = threadIdx.x;
    const int lane = tid & 31;
    const int wid  = tid >> 5;
    const int q0   = (gridDim.x - 1 - blockIdx.x) * 128;   // longest first
    const int h    = blockIdx.y;
    const int b    = blockIdx.z;
    const int kvh  = h >> 2;
    const uint32_t sb = s2u(sa);
    const uint32_t QHo = sb;
    const uint32_t QLo = sb + QT * 2;

    {
        const __nv_bfloat16* qgh = Qh + (((size_t)b * SS + q0) * HH + h) * DHD;
        const __nv_bfloat16* qgl = Ql + (((size_t)b * SS + q0) * HH + h) * DHD;
#pragma unroll
        for (int t = 0; t < 8; t++) {
            int idx = tid + t * 256;
            int row = idx >> 4;
            int c   = idx & 15;
            uint32_t off = (uint32_t)(row * AP + c * 8) * 2;
            size_t g = (size_t)row * (HH * DHD) + c * 8;
            CP16(QHo + off, qgh + g);
            CP16(QLo + off, qgl + g);
        }
        CP_COMMIT();
    }

    const int kv_end = min(q0 + 256, SS);
    const int nblk   = kv_end >> 6;
    const uint32_t stg0 = sb + 2 * QT * 2;

    attn_load_kv(Kh, Kl, Vh, Vl, b, kvh, 0, stg0, tid);

    float oacc[16][4];
#pragma unroll
    for (int df = 0; df < 16; df++)
#pragma unroll
        for (int r = 0; r < 4; r++) oacc[df][r] = 0.f;
    float m0r = -1e30f, m1r = -1e30f, l0r = 0.f, l1r = 0.f;

    const int r0 = wid * 16;

    for (int blk = 0; blk < nblk; blk++) {
        if (blk + 1 < nblk) {
            attn_load_kv(Kh, Kl, Vh, Vl, b, kvh, (blk + 1) * 64,
                         stg0 + (uint32_t)(((blk + 1) & 1) * STG) * 2, tid);
            CP_WAIT1();
        } else {
            CP_WAIT0();
        }
        __syncthreads();

        const uint32_t kb = stg0 + (uint32_t)((blk & 1) * STG) * 2;
        const uint32_t vb = kb + 2 * KVT * 2;

        float sacc[8][4];
#pragma unroll
        for (int nf = 0; nf < 8; nf++)
#pragma unroll
            for (int r = 0; r < 4; r++) sacc[nf][r] = 0.f;

#pragma unroll
        for (int ks = 0; ks < 8; ks++) {
            uint32_t ah[4], al[4];
            uint32_t qa = QHo + (uint32_t)((r0 + (lane & 15)) * AP +
                                           ks * 16 + ((lane >> 4) << 3)) * 2;
            LDM_X4(ah, qa);
            LDM_X4(al, qa + QT * 2);
#pragma unroll
            for (int np = 0; np < 4; np++) {
                uint32_t bh[4], bl[4];
                uint32_t ba = kb + (uint32_t)((np * 16 + (lane & 7) + ((lane >> 4) & 1) * 8) * AP +
                                              ks * 16 + ((lane >> 3) & 1) * 8) * 2;
                LDM_X4(bh, ba);
                LDM_X4(bl, ba + KVT * 2);
                MMA16816(sacc[2 * np],     ah, &bh[0]);
                MMA16816(sacc[2 * np],     ah, &bl[0]);
                MMA16816(sacc[2 * np],     al, &bh[0]);
                MMA16816(sacc[2 * np + 1], ah, &bh[2]);
                MMA16816(sacc[2 * np + 1], ah, &bl[2]);
                MMA16816(sacc[2 * np + 1], al, &bh[2]);
            }
        }

        const int j0 = blk * 64;
        if (j0 + 63 > q0 + WIN) {
            const int rq = q0 + r0 + (lane >> 2);
#pragma unroll
            for (int nf = 0; nf < 8; nf++) {
#pragma unroll
                for (int e = 0; e < 2; e++) {
                    int k = j0 + nf * 8 + (lane & 3) * 2 + e;
                    if (k > rq + WIN)     sacc[nf][e]     = -1e30f;
                    if (k > rq + 8 + WIN) sacc[nf][2 + e] = -1e30f;
                }
            }
        }

        float mx0 = -1e30f, mx1 = -1e30f;
#pragma unroll
        for (int nf = 0; nf < 8; nf++) {
            mx0 = fmaxf(mx0, fmaxf(sacc[nf][0], sacc[nf][1]));
            mx1 = fmaxf(mx1, fmaxf(sacc[nf][2], sacc[nf][3]));
        }
        mx0 = fmaxf(mx0, __shfl_xor_sync(0xffffffffu, mx0, 1));
        mx0 = fmaxf(mx0, __shfl_xor_sync(0xffffffffu, mx0, 2));
        mx1 = fmaxf(mx1, __shfl_xor_sync(0xffffffffu, mx1, 1));
        mx1 = fmaxf(mx1, __shfl_xor_sync(0xffffffffu, mx1, 2));
        float mn0 = fmaxf(m0r, mx0), mn1 = fmaxf(m1r, mx1);
        float a0 = __expf(m0r - mn0), a1 = __expf(m1r - mn1);
        m0r = mn0; m1r = mn1;
        float s0 = 0.f, s1 = 0.f;
#pragma unroll
        for (int nf = 0; nf < 8; nf++) {
            sacc[nf][0] = __expf(sacc[nf][0] - mn0);
            sacc[nf][1] = __expf(sacc[nf][1] - mn0);
            sacc[nf][2] = __expf(sacc[nf][2] - mn1);
            sacc[nf][3] = __expf(sacc[nf][3] - mn1);
            s0 += sacc[nf][0] + sacc[nf][1];
            s1 += sacc[nf][2] + sacc[nf][3];
        }
        s0 += __shfl_xor_sync(0xffffffffu, s0, 1);
        s0 += __shfl_xor_sync(0xffffffffu, s0, 2);
        s1 += __shfl_xor_sync(0xffffffffu, s1, 1);
        s1 += __shfl_xor_sync(0xffffffffu, s1, 2);
        l0r = l0r * a0 + s0;
        l1r = l1r * a1 + s1;
#pragma unroll
        for (int df = 0; df < 16; df++) {
            oacc[df][0] *= a0; oacc[df][1] *= a0;
            oacc[df][2] *= a1; oacc[df][3] *= a1;
        }

#pragma unroll
        for (int kk = 0; kk < 4; kk++) {
            const float* f0 = sacc[2 * kk];
            const float* f1 = sacc[2 * kk + 1];
            uint32_t ph[4], pl[4];
            ph[0] = bf2(f0[0], f0[1]); ph[1] = bf2(f0[2], f0[3]);
            ph[2] = bf2(f1[0], f1[1]); ph[3] = bf2(f1[2], f1[3]);
            pl[0] = bf2(bfres(f0[0]), bfres(f0[1]));
            pl[1] = bf2(bfres(f0[2]), bfres(f0[3]));
            pl[2] = bf2(bfres(f1[0]), bfres(f1[1]));
            pl[3] = bf2(bfres(f1[2]), bfres(f1[3]));
#pragma unroll
            for (int dp = 0; dp < 8; dp++) {
                uint32_t bvh[4], bvl[4];
                uint32_t va = vb + (uint32_t)((kk * 16 + (lane & 15)) * AP +
                                              dp * 16 + ((lane >> 4) << 3)) * 2;
                LDM_X4_T(bvh, va);
                LDM_X4_T(bvl, va + KVT * 2);
                MMA16816(oacc[2 * dp],     ph, &bvh[0]);
                MMA16816(oacc[2 * dp],     ph, &bvl[0]);
                MMA16816(oacc[2 * dp],     pl, &bvh[0]);
                MMA16816(oacc[2 * dp + 1], ph, &bvh[2]);
                MMA16816(oacc[2 * dp + 1], ph, &bvl[2]);
                MMA16816(oacc[2 * dp + 1], pl, &bvh[2]);
            }
        }
        __syncthreads();
    }

    const float inv0 = 1.0f / l0r;
    const float inv1 = 1.0f / l1r;
    const int rq = q0 + r0 + (lane >> 2);
    size_t base0 = (((size_t)b * SS + rq) * HH + h) * DHD;
    size_t base1 = base0 + (size_t)8 * HH * DHD;
#pragma unroll
    for (int df = 0; df < 16; df++) {
        int col = df * 8 + (lane & 3) * 2;
        float v0 = oacc[df][0] * inv0, v1 = oacc[df][1] * inv0;
        float v2 = oacc[df][2] * inv1, v3 = oacc[df][3] * inv1;
        __nv_bfloat16 h0 = __float2bfloat16(v0), h1 = __float2bfloat16(v1);
        __nv_bfloat16 h2 = __float2bfloat16(v2), h3 = __float2bfloat16(v3);
        *(__nv_bfloat162*)(Ohi + base0 + col) = __nv_bfloat162(h0, h1);
        *(__nv_bfloat162*)(Ohi + base1 + col) = __nv_bfloat162(h2, h3);
        *(__nv_bfloat162*)(Olo + base0 + col) = __nv_bfloat162(
            __float2bfloat16(v0 - __bfloat162float(h0)),
            __float2bfloat16(v1 - __bfloat162float(h1)));
        *(__nv_bfloat162*)(Olo + base1 + col) = __nv_bfloat162(
            __float2bfloat16(v2 - __bfloat162float(h2)),
            __float2bfloat16(v3 - __bfloat162float(h3)));
    }
}

// ---------------- launch ----------------------------------------------------
extern "C" void kernel_launch(void* const* d_in, const int* in_sizes, int n_in,
                              void* d_out, int out_size) {
    const float* x  = (const float*)d_in[0];
    const float* Wq = (const float*)d_in[1];
    const float* Wk = (const float*)d_in[2];
    const float* Wv = (const float*)d_in[3];
    const float* Wo = (const float*)d_in[4];
    float* out = (float*)d_out;

    void *pxh, *pxl, *pqh, *pql, *pkh, *pkl, *pvh, *pvl, *poh, *pol, *pah, *pal;
    void *aqh, *aql, *akh, *akl, *avh, *avl;
    cudaGetSymbolAddress(&pxh, g_xhi);  cudaGetSymbolAddress(&pxl, g_xlo);
    cudaGetSymbolAddress(&pqh, g_wqhi); cudaGetSymbolAddress(&pql, g_wqlo);
    cudaGetSymbolAddress(&pkh, g_wkhi); cudaGetSymbolAddress(&pkl, g_wklo);
    cudaGetSymbolAddress(&pvh, g_wvhi); cudaGetSymbolAddress(&pvl, g_wvlo);
    cudaGetSymbolAddress(&poh, g_wohi); cudaGetSymbolAddress(&pol, g_wolo);
    cudaGetSymbolAddress(&pah, g_ahi);  cudaGetSymbolAddress(&pal, g_alo);
    cudaGetSymbolAddress(&aqh, g_qah);  cudaGetSymbolAddress(&aql, g_qal);
    cudaGetSymbolAddress(&akh, g_kah);  cudaGetSymbolAddress(&akl, g_kal);
    cudaGetSymbolAddress(&avh, g_vah);  cudaGetSymbolAddress(&avl, g_val);

    cudaFuncSetAttribute(gemm_qkv,
                         cudaFuncAttributeMaxDynamicSharedMemorySize, GEMM_SMEM_B);
    cudaFuncSetAttribute(gemm_mma,
                         cudaFuncAttributeMaxDynamicSharedMemorySize, GEMM_SMEM_B);
    cudaFuncSetAttribute(attn_mma,
                         cudaFuncAttributeMaxDynamicSharedMemorySize, ATT_SMEM_B);

    // 1. RoPE tables
    rope_tables_kernel<<<(SS * 64 + 255) / 256, 256>>>();

    // 2. All hi/lo splits in one launch
    split_all_kernel<<<X4B + WQ4B + WK4B + WV4B + WO4B, 256>>>(
        x,  (__nv_bfloat16*)pxh, (__nv_bfloat16*)pxl,
        Wq, (__nv_bfloat16*)pqh, (__nv_bfloat16*)pql,
        Wk, (__nv_bfloat16*)pkh, (__nv_bfloat16*)pkl,
        Wv, (__nv_bfloat16*)pvh, (__nv_bfloat16*)pvl,
        Wo, (__nv_bfloat16*)poh, (__nv_bfloat16*)pol);

    // 3. Fused Q/K/V projections with RoPE+split epilogue
    gemm_qkv<<<dim3(24, MTOK / 128), 256, GEMM_SMEM_B>>>(
        (const __nv_bfloat16*)pxh, (const __nv_bfloat16*)pxl,
        (const __nv_bfloat16*)pqh, (const __nv_bfloat16*)pql,
        (const __nv_bfloat16*)pkh, (const __nv_bfloat16*)pkl,
        (const __nv_bfloat16*)pvh, (const __nv_bfloat16*)pvl,
        (__nv_bfloat16*)aqh, (__nv_bfloat16*)aql,
        (__nv_bfloat16*)akh, (__nv_bfloat16*)akl,
        (__nv_bfloat16*)avh, (__nv_bfloat16*)avl);

    // 4. Attention -> bf16 hi/lo
    attn_mma<<<dim3(SS / 128, HH, BB), 256, ATT_SMEM_B>>>(
        (const __nv_bfloat16*)aqh, (const __nv_bfloat16*)aql,
        (const __nv_bfloat16*)akh, (const __nv_bfloat16*)akl,
        (const __nv_bfloat16*)avh, (const __nv_bfloat16*)avl,
        (__nv_bfloat16*)pah, (__nv_bfloat16*)pal);

    // 5. O projection
    gemm_mma<<<dim3(DD / 128, MTOK / 128), 256, GEMM_SMEM_B>>>(
        (const __nv_bfloat16*)pah, (const __nv_bfloat16*)pal,
        (const __nv_bfloat16*)poh, (const __nv_bfloat16*)pol,
        out, MTOK, DD, NQ);
}

// round 10
// speedup vs baseline: 3.0211x; 1.0185x over previous
#include <cuda_runtime.h>
#include <cuda_bf16.h>
#include <math.h>
#include <stdint.h>

// Problem constants
#define BB    2
#define SS    2048
#define DD    2048
#define HH    16
#define KVH   4
#define DHD   128
#define WIN   128
#define MTOK  (BB*SS)          // 4096 tokens
#define NQ    (HH*DHD)         // 2048
#define NKV   (KVH*DHD)        // 512

// ---------------- scratch (device globals; no allocation allowed) ----------
__device__ float g_cos[SS * 64];
__device__ float g_sin[SS * 64];
__device__ __align__(256) __nv_bfloat16 g_xhi[MTOK * DD],  g_xlo[MTOK * DD];
__device__ __align__(256) __nv_bfloat16 g_wqhi[NQ * DD],   g_wqlo[NQ * DD];
__device__ __align__(256) __nv_bfloat16 g_wkhi[NKV * DD],  g_wklo[NKV * DD];
__device__ __align__(256) __nv_bfloat16 g_wvhi[NKV * DD],  g_wvlo[NKV * DD];
__device__ __align__(256) __nv_bfloat16 g_wohi[DD * NQ],   g_wolo[DD * NQ];
__device__ __align__(256) __nv_bfloat16 g_ahi[MTOK * NQ],  g_alo[MTOK * NQ];
__device__ __align__(256) __nv_bfloat16 g_qah[MTOK * NQ],  g_qal[MTOK * NQ];
__device__ __align__(256) __nv_bfloat16 g_kah[MTOK * NKV], g_kal[MTOK * NKV];
__device__ __align__(256) __nv_bfloat16 g_vah[MTOK * NKV], g_val[MTOK * NKV];

// ---------------- RoPE tables ----------------------------------------------
__global__ void rope_tables_kernel() {
    int idx = blockIdx.x * blockDim.x + threadIdx.x;
    if (idx >= SS * 64) return;
    int s = idx >> 6;
    int j = idx & 63;
    double freq = exp(-((double)(2 * j) / 128.0) * 9.210340371976184); // ln(10000)
    double a = (double)s * freq;
    g_cos[idx] = (float)cos(a);
    g_sin[idx] = (float)sin(a);
}

// ---------------- merged hi/lo bf16 split (5 tensors, one launch) -----------
#define X4B   8192
#define WQ4B  4096
#define WK4B  1024
#define WV4B  1024
#define WO4B  4096

__device__ __forceinline__ void split_one(const float* __restrict__ src,
                                          __nv_bfloat16* __restrict__ hi,
                                          __nv_bfloat16* __restrict__ lo, int i) {
    float4 v = ((const float4*)src)[i];
    __nv_bfloat16 h0 = __float2bfloat16(v.x);
    __nv_bfloat16 h1 = __float2bfloat16(v.y);
    __nv_bfloat16 h2 = __float2bfloat16(v.z);
    __nv_bfloat16 h3 = __float2bfloat16(v.w);
    __nv_bfloat162* ph = (__nv_bfloat162*)hi;
    __nv_bfloat162* pl = (__nv_bfloat162*)lo;
    ph[2 * i]     = __nv_bfloat162(h0, h1);
    ph[2 * i + 1] = __nv_bfloat162(h2, h3);
    pl[2 * i]     = __nv_bfloat162(__float2bfloat16(v.x - __bfloat162float(h0)),
                                   __float2bfloat16(v.y - __bfloat162float(h1)));
    pl[2 * i + 1] = __nv_bfloat162(__float2bfloat16(v.z - __bfloat162float(h2)),
                                   __float2bfloat16(v.w - __bfloat162float(h3)));
}

__global__ void split_all_kernel(
    const float* __restrict__ x,  __nv_bfloat16* xh, __nv_bfloat16* xl,
    const float* __restrict__ wq, __nv_bfloat16* qh, __nv_bfloat16* ql,
    const float* __restrict__ wk, __nv_bfloat16* kh, __nv_bfloat16* kl,
    const float* __restrict__ wv, __nv_bfloat16* vh, __nv_bfloat16* vl,
    const float* __restrict__ wo, __nv_bfloat16* oh, __nv_bfloat16* ol) {
    int bx = blockIdx.x;
    int t  = threadIdx.x;
    if (bx < X4B) {
        split_one(x, xh, xl, bx * 256 + t);
    } else if (bx < X4B + WQ4B) {
        split_one(wq, qh, ql, (bx - X4B) * 256 + t);
    } else if (bx < X4B + WQ4B + WK4B) {
        split_one(wk, kh, kl, (bx - X4B - WQ4B) * 256 + t);
    } else if (bx < X4B + WQ4B + WK4B + WV4B) {
        split_one(wv, vh, vl, (bx - X4B - WQ4B - WK4B) * 256 + t);
    } else {
        split_one(wo, oh, ol, (bx - X4B - WQ4B - WK4B - WV4B) * 256 + t);
    }
}

// ---------------- PTX helpers (non-'a' features only) ------------------------
__device__ __forceinline__ uint32_t s2u(const void* p) {
    uint32_t a;
    asm("{ .reg .u64 t; cvta.to.shared.u64 t, %1; cvt.u32.u64 %0, t; }"
        : "=r"(a) : "l"(p));
    return a;
}

#define CP16(saddr, gptr) \
    asm volatile("cp.async.cg.shared.global [%0], [%1], 16;" \
                 :: "r"(saddr), "l"(gptr))
#define CP_COMMIT() asm volatile("cp.async.commit_group;" ::: "memory")
#define CP_WAIT0()  asm volatile("cp.async.wait_group 0;" ::: "memory")
#define CP_WAIT1()  asm volatile("cp.async.wait_group 1;" ::: "memory")

#define LDM_X4(R, addr) \
    asm volatile("ldmatrix.sync.aligned.m8n8.x4.shared.b16 {%0,%1,%2,%3}, [%4];" \
                 : "=r"((R)[0]), "=r"((R)[1]), "=r"((R)[2]), "=r"((R)[3]) \
                 : "r"(addr))
#define LDM_X4_T(R, addr) \
    asm volatile("ldmatrix.sync.aligned.m8n8.x4.trans.shared.b16 {%0,%1,%2,%3}, [%4];" \
                 : "=r"((R)[0]), "=r"((R)[1]), "=r"((R)[2]), "=r"((R)[3]) \
                 : "r"(addr))

#define MMA16816(C, A, B) \
    asm volatile("mma.sync.aligned.m16n8k16.row.col.f32.bf16.bf16.f32 " \
                 "{%0,%1,%2,%3}, {%4,%5,%6,%7}, {%8,%9}, {%0,%1,%2,%3};" \
                 : "+f"((C)[0]), "+f"((C)[1]), "+f"((C)[2]), "+f"((C)[3]) \
                 : "r"((A)[0]), "r"((A)[1]), "r"((A)[2]), "r"((A)[3]), \
                   "r"((B)[0]), "r"((B)[1]))

__device__ __forceinline__ uint32_t bf2(float lo, float hi) {
    uint32_t r;
    asm("cvt.rn.bf16x2.f32 %0, %1, %2;" : "=r"(r) : "f"(hi), "f"(lo));
    return r;
}
__device__ __forceinline__ float bfres(float x) {
    return x - __bfloat162float(__float2bfloat16(x));
}
__device__ __forceinline__ float ex2(float x) {
    float r;
    asm("ex2.approx.ftz.f32 %0, %1;" : "=f"(r) : "f"(x));
    return r;
}

// ---------------- mma.sync GEMM core (BK=64, pitch 72) -----------------------
#define BKC   64
#define SAPD  72
#define TILE_ELE  (128 * SAPD)       // 9216
#define STAGE_ELE (4 * TILE_ELE)     // 36864
#define GEMM_SMEM_B (2 * STAGE_ELE * 2)   // 147456 bytes

__device__ __forceinline__ void gemm_load_stage(
    const __nv_bfloat16* __restrict__ Ahi, const __nv_bfloat16* __restrict__ Alo,
    const __nv_bfloat16* __restrict__ Bhi, const __nv_bfloat16* __restrict__ Blo,
    int K, int m0, int n0, int k0, uint32_t sdst, int tid) {
#pragma unroll
    for (int t = 0; t < 4; t++) {
        int idx = tid + t * 256;       // 0..1023
        int row = idx >> 3;            // 0..127
        int c8  = idx & 7;
        uint32_t so = sdst + (uint32_t)(row * SAPD + c8 * 8) * 2;
        size_t aoff = (size_t)(m0 + row) * K + k0 + c8 * 8;
        size_t boff = (size_t)(n0 + row) * K + k0 + c8 * 8;
        CP16(so,                    Ahi + aoff);
        CP16(so + TILE_ELE * 2,     Alo + aoff);
        CP16(so + 2 * TILE_ELE * 2, Bhi + boff);
        CP16(so + 3 * TILE_ELE * 2, Blo + boff);
    }
    CP_COMMIT();
}

__device__ __forceinline__ void gemm_mainloop(
    const __nv_bfloat16* __restrict__ Ahi, const __nv_bfloat16* __restrict__ Alo,
    const __nv_bfloat16* __restrict__ Bhi, const __nv_bfloat16* __restrict__ Blo,
    int K, int m0, int n0, uint32_t sbase, int tid, int lane, int wm, int wn,
    float acc[4][4][4]) {
    const int nchunk = K / BKC;
    gemm_load_stage(Ahi, Alo, Bhi, Blo, K, m0, n0, 0, sbase, tid);

    for (int c = 0; c < nchunk; c++) {
        if (c + 1 < nchunk) {
            gemm_load_stage(Ahi, Alo, Bhi, Blo, K, m0, n0, (c + 1) * BKC,
                            sbase + (uint32_t)(((c + 1) & 1) * STAGE_ELE) * 2, tid);
            CP_WAIT1();
        } else {
            CP_WAIT0();
        }
        __syncthreads();

        const uint32_t sa = sbase + (uint32_t)((c & 1) * STAGE_ELE) * 2;
        const uint32_t sb = sa + 2 * TILE_ELE * 2;
#pragma unroll
        for (int ks = 0; ks < 4; ks++) {
            uint32_t ah[4][4], al[4][4];
#pragma unroll
            for (int mi = 0; mi < 4; mi++) {
                int r  = wm + mi * 16 + (lane & 15);
                int cc = ks * 16 + ((lane >> 4) << 3);
                uint32_t ad = sa + (uint32_t)(r * SAPD + cc) * 2;
                LDM_X4(ah[mi], ad);
                LDM_X4(al[mi], ad + TILE_ELE * 2);
            }
            uint32_t bh[2][4], bl[2][4];
#pragma unroll
            for (int np = 0; np < 2; np++) {
                int r  = wn + np * 16 + (lane & 7) + ((lane >> 4) & 1) * 8;
                int cc = ks * 16 + ((lane >> 3) & 1) * 8;
                uint32_t ad = sb + (uint32_t)(r * SAPD + cc) * 2;
                LDM_X4(bh[np], ad);
                LDM_X4(bl[np], ad + TILE_ELE * 2);
            }
#pragma unroll
            for (int mi = 0; mi < 4; mi++)
#pragma unroll
                for (int np = 0; np < 2; np++) {
                    MMA16816(acc[mi][2 * np],     ah[mi], &bh[np][0]);
                    MMA16816(acc[mi][2 * np],     ah[mi], &bl[np][0]);
                    MMA16816(acc[mi][2 * np],     al[mi], &bh[np][0]);
                    MMA16816(acc[mi][2 * np + 1], ah[mi], &bh[np][2]);
                    MMA16816(acc[mi][2 * np + 1], ah[mi], &bl[np][2]);
                    MMA16816(acc[mi][2 * np + 1], al[mi], &bh[np][2]);
                }
        }
        __syncthreads();
    }
}

// ---------------- fused QKV GEMM with RoPE+split epilogue --------------------
__global__ __launch_bounds__(256)
void gemm_qkv(const __nv_bfloat16* __restrict__ Xhi, const __nv_bfloat16* __restrict__ Xlo,
              const __nv_bfloat16* __restrict__ WQh, const __nv_bfloat16* __restrict__ WQl,
              const __nv_bfloat16* __restrict__ WKh, const __nv_bfloat16* __restrict__ WKl,
              const __nv_bfloat16* __restrict__ WVh, const __nv_bfloat16* __restrict__ WVl,
              __nv_bfloat16* __restrict__ Qhi, __nv_bfloat16* __restrict__ Qlo,
              __nv_bfloat16* __restrict__ Khi, __nv_bfloat16* __restrict__ Klo,
              __nv_bfloat16* __restrict__ Vhi, __nv_bfloat16* __restrict__ Vlo) {
    extern __shared__ __nv_bfloat16 smb[];
    const int tid  = threadIdx.x;
    const int lane = tid & 31;
    const int wid  = tid >> 5;
    const int wm   = (wid & 1) * 64;
    const int wn   = (wid >> 1) * 32;
    const int m0 = blockIdx.y * 128;
    const int bx = blockIdx.x;
    const uint32_t sbase = s2u(smb);

    const __nv_bfloat16 *Bh, *Bl;
    int n0, mode, head, nheads;
    __nv_bfloat16 *Oh, *Ol;
    float scl;
    if (bx < 16) {        // Q: rope + softmax scale * log2(e)  (exp2 softmax)
        Bh = WQh; Bl = WQl; n0 = bx * 128;
        mode = 0; head = bx; nheads = HH; Oh = Qhi; Ol = Qlo;
        scl = 0.1275240743932331f;   // (1/sqrt(128)) * log2(e)
    } else if (bx < 20) { // K: rope
        Bh = WKh; Bl = WKl; n0 = (bx - 16) * 128;
        mode = 0; head = bx - 16; nheads = KVH; Oh = Khi; Ol = Klo;
        scl = 1.0f;
    } else {              // V: direct hi/lo
        Bh = WVh; Bl = WVl; n0 = (bx - 20) * 128;
        mode = 1; head = bx - 20; nheads = KVH; Oh = Vhi; Ol = Vlo;
        scl = 1.0f;
    }

    float acc[4][4][4];
#pragma unroll
    for (int mi = 0; mi < 4; mi++)
#pragma unroll
        for (int ni = 0; ni < 4; ni++)
#pragma unroll
            for (int r = 0; r < 4; r++) acc[mi][ni][r] = 0.f;

    gemm_mainloop(Xhi, Xlo, Bh, Bl, DD, m0, n0, sbase, tid, lane, wm, wn, acc);

    if (mode == 1) {
        const int row0 = wm + (lane >> 2);
        const int col0 = wn + (lane & 3) * 2;
#pragma unroll
        for (int mi = 0; mi < 4; mi++)
#pragma unroll
            for (int ni = 0; ni < 4; ni++) {
                size_t o0 = (size_t)(m0 + row0 + mi * 16) * NKV + head * DHD + col0 + ni * 8;
                size_t o1 = o0 + (size_t)8 * NKV;
                float a0 = acc[mi][ni][0], a1 = acc[mi][ni][1];
                float a2 = acc[mi][ni][2], a3 = acc[mi][ni][3];
                __nv_bfloat16 h0 = __float2bfloat16(a0), h1 = __float2bfloat16(a1);
                __nv_bfloat16 h2 = __float2bfloat16(a2), h3 = __float2bfloat16(a3);
                *(__nv_bfloat162*)(Oh + o0) = __nv_bfloat162(h0, h1);
                *(__nv_bfloat162*)(Oh + o1) = __nv_bfloat162(h2, h3);
                *(__nv_bfloat162*)(Ol + o0) = __nv_bfloat162(
                    __float2bfloat16(a0 - __bfloat162float(h0)),
                    __float2bfloat16(a1 - __bfloat162float(h1)));
                *(__nv_bfloat162*)(Ol + o1) = __nv_bfloat162(
                    __float2bfloat16(a2 - __bfloat162float(h2)),
                    __float2bfloat16(a3 - __bfloat162float(h3)));
            }
        return;
    }

    // Q/K: stage fp32 tile in smem, apply RoPE, emit hi/lo bf16
    float* stage = (float*)smb;
    {
        const int rl = wm + (lane >> 2);
        const int cl = wn + (lane & 3) * 2;
#pragma unroll
        for (int mi = 0; mi < 4; mi++)
#pragma unroll
            for (int ni = 0; ni < 4; ni++) {
                stage[(rl + mi * 16) * 128 + cl + ni * 8]     = acc[mi][ni][0];
                stage[(rl + mi * 16) * 128 + cl + ni * 8 + 1] = acc[mi][ni][1];
                stage[(rl + mi * 16 + 8) * 128 + cl + ni * 8]     = acc[mi][ni][2];
                stage[(rl + mi * 16 + 8) * 128 + cl + ni * 8 + 1] = acc[mi][ni][3];
            }
    }
    __syncthreads();

#pragma unroll 2
    for (int it = 0; it < 16; it++) {
        int row = it * 8 + wid;
        int pos = (m0 + row) & (SS - 1);
        float x0a = stage[row * 128 + 2 * lane];
        float x0b = stage[row * 128 + 2 * lane + 1];
        float x1a = stage[row * 128 + 2 * lane + 64];
        float x1b = stage[row * 128 + 2 * lane + 65];
        float c0 = g_cos[pos * 64 + lane],      s0 = g_sin[pos * 64 + lane];
        float c1 = g_cos[pos * 64 + 32 + lane], s1 = g_sin[pos * 64 + 32 + lane];
        float y0a = (x0a * c0 - x1a * s0) * scl;
        float y0b = (x0b * c0 - x1b * s0) * scl;
        float y1a = (x1a * c1 + x0a * s1) * scl;
        float y1b = (x1b * c1 + x0b * s1) * scl;
        __nv_bfloat16 h0a = __float2bfloat16(y0a), h0b = __float2bfloat16(y0b);
        __nv_bfloat16 h1a = __float2bfloat16(y1a), h1b = __float2bfloat16(y1b);
        size_t gb = (size_t)(m0 + row) * (nheads * DHD) + head * DHD;
        *(__nv_bfloat162*)(Oh + gb + 2 * lane)      = __nv_bfloat162(h0a, h0b);
        *(__nv_bfloat162*)(Oh + gb + 2 * lane + 64) = __nv_bfloat162(h1a, h1b);
        *(__nv_bfloat162*)(Ol + gb + 2 * lane) = __nv_bfloat162(
            __float2bfloat16(y0a - __bfloat162float(h0a)),
            __float2bfloat16(y0b - __bfloat162float(h0b)));
        *(__nv_bfloat162*)(Ol + gb + 2 * lane + 64) = __nv_bfloat162(
            __float2bfloat16(y1a - __bfloat162float(h1a)),
            __float2bfloat16(y1b - __bfloat162float(h1b)));
    }
}

// ---------------- O-projection GEMM (fp32 out) -------------------------------
__global__ __launch_bounds__(256)
void gemm_mma(const __nv_bfloat16* __restrict__ Ahi, const __nv_bfloat16* __restrict__ Alo,
              const __nv_bfloat16* __restrict__ Bhi, const __nv_bfloat16* __restrict__ Blo,
              float* __restrict__ C, int M, int N, int K) {
    extern __shared__ __nv_bfloat16 smb[];
    const int tid  = threadIdx.x;
    const int lane = tid & 31;
    const int wid  = tid >> 5;
    const int wm   = (wid & 1) * 64;
    const int wn   = (wid >> 1) * 32;
    const int m0 = blockIdx.y * 128;
    const int n0 = blockIdx.x * 128;
    const uint32_t sbase = s2u(smb);

    float acc[4][4][4];
#pragma unroll
    for (int mi = 0; mi < 4; mi++)
#pragma unroll
        for (int ni = 0; ni < 4; ni++)
#pragma unroll
            for (int r = 0; r < 4; r++) acc[mi][ni][r] = 0.f;

    gemm_mainloop(Ahi, Alo, Bhi, Blo, K, m0, n0, sbase, tid, lane, wm, wn, acc);

    const int row0 = m0 + wm + (lane >> 2);
    const int col0 = n0 + wn + (lane & 3) * 2;
#pragma unroll
    for (int mi = 0; mi < 4; mi++)
#pragma unroll
        for (int ni = 0; ni < 4; ni++) {
            float* p0 = C + (size_t)(row0 + mi * 16) * N + col0 + ni * 8;
            float* p1 = C + (size_t)(row0 + mi * 16 + 8) * N + col0 + ni * 8;
            *(float2*)p0 = make_float2(acc[mi][ni][0], acc[mi][ni][1]);
            *(float2*)p1 = make_float2(acc[mi][ni][2], acc[mi][ni][3]);
        }
}

// ---------------- Flash attention on mma.sync --------------------------------
#define AP   136
#define QT   (128 * AP)
#define KVT  (64 * AP)
#define STG  (4 * KVT)
#define ATT_SMEM_B ((2 * QT + 2 * STG) * 2)   // 208896 bytes

__device__ __forceinline__ void attn_load_kv(
    const __nv_bfloat16* __restrict__ Kh, const __nv_bfloat16* __restrict__ Kl,
    const __nv_bfloat16* __restrict__ Vh, const __nv_bfloat16* __restrict__ Vl,
    int b, int kvh, int j0, uint32_t base, int tid) {
#pragma unroll
    for (int t = 0; t < 4; t++) {
        int idx = tid + t * 256;
        int row = idx >> 4;
        int c   = idx & 15;
        uint32_t off = (uint32_t)(row * AP + c * 8) * 2;
        size_t g = ((size_t)(b * SS + j0 + row) * KVH + kvh) * DHD + c * 8;
        CP16(base + off,               Kh + g);
        CP16(base + KVT * 2 + off,     Kl + g);
        CP16(base + 2 * KVT * 2 + off, Vh + g);
        CP16(base + 3 * KVT * 2 + off, Vl + g);
    }
    CP_COMMIT();
}

__global__ __launch_bounds__(256, 1)
void attn_mma(const __nv_bfloat16* __restrict__ Qh, const __nv_bfloat16* __restrict__ Ql,
              const __nv_bfloat16* __restrict__ Kh, const __nv_bfloat16* __restrict__ Kl,
              const __nv_bfloat16* __restrict__ Vh, const __nv_bfloat16* __restrict__ Vl,
              __nv_bfloat16* __restrict__ Ohi, __nv_bfloat16* __restrict__ Olo) {
    extern __shared__ __nv_bfloat16 sa[];
    const int tid  = threadIdx.x;
    const int lane = tid & 31;
    const int wid  = tid >> 5;
    const int q0   = (gridDim.x - 1 - blockIdx.x) * 128;   // longest first
    const int h    = blockIdx.y;
    const int b    = blockIdx.z;
    const int kvh  = h >> 2;
    const uint32_t sb = s2u(sa);
    const uint32_t QHo = sb;
    const uint32_t QLo = sb + QT * 2;

    {
        const __nv_bfloat16* qgh = Qh + (((size_t)b * SS + q0) * HH + h) * DHD;
        const __nv_bfloat16* qgl = Ql + (((size_t)b * SS + q0) * HH + h) * DHD;
#pragma unroll
        for (int t = 0; t < 8; t++) {
            int idx = tid + t * 256;
            int row = idx >> 4;
            int c   = idx & 15;
            uint32_t off = (uint32_t)(row * AP + c * 8) * 2;
            size_t g = (size_t)row * (HH * DHD) + c * 8;
            CP16(QHo + off, qgh + g);
            CP16(QLo + off, qgl + g);
        }
        CP_COMMIT();
    }

    const int kv_end = min(q0 + 256, SS);
    const int nblk   = kv_end >> 6;
    const uint32_t stg0 = sb + 2 * QT * 2;

    attn_load_kv(Kh, Kl, Vh, Vl, b, kvh, 0, stg0, tid);

    const int r0 = wid * 16;

    // hoist Q-hi fragments into registers (reused for every KV block)
    CP_WAIT1();          // Q group complete (KV0 may still be pending)
    __syncthreads();
    uint32_t qhf[8][4];
#pragma unroll
    for (int ks = 0; ks < 8; ks++) {
        uint32_t qa = QHo + (uint32_t)((r0 + (lane & 15)) * AP +
                                       ks * 16 + ((lane >> 4) << 3)) * 2;
        LDM_X4(qhf[ks], qa);
    }

    float oacc[16][4];
#pragma unroll
    for (int df = 0; df < 16; df++)
#pragma unroll
        for (int r = 0; r < 4; r++) oacc[df][r] = 0.f;
    float m0r = -1e30f, m1r = -1e30f, l0r = 0.f, l1r = 0.f;

    for (int blk = 0; blk < nblk; blk++) {
        if (blk + 1 < nblk) {
            attn_load_kv(Kh, Kl, Vh, Vl, b, kvh, (blk + 1) * 64,
                         stg0 + (uint32_t)(((blk + 1) & 1) * STG) * 2, tid);
            CP_WAIT1();
        } else {
            CP_WAIT0();
        }
        __syncthreads();

        const uint32_t kb = stg0 + (uint32_t)((blk & 1) * STG) * 2;
        const uint32_t vb = kb + 2 * KVT * 2;

        float sacc[8][4];
#pragma unroll
        for (int nf = 0; nf < 8; nf++)
#pragma unroll
            for (int r = 0; r < 4; r++) sacc[nf][r] = 0.f;

#pragma unroll
        for (int ks = 0; ks < 8; ks++) {
            uint32_t al[4];
            uint32_t qa = QLo + (uint32_t)((r0 + (lane & 15)) * AP +
                                           ks * 16 + ((lane >> 4) << 3)) * 2;
            LDM_X4(al, qa);
#pragma unroll
            for (int np = 0; np < 4; np++) {
                uint32_t bh[4], bl[4];
                uint32_t ba = kb + (uint32_t)((np * 16 + (lane & 7) + ((lane >> 4) & 1) * 8) * AP +
                                              ks * 16 + ((lane >> 3) & 1) * 8) * 2;
                LDM_X4(bh, ba);
                LDM_X4(bl, ba + KVT * 2);
                MMA16816(sacc[2 * np],     qhf[ks], &bh[0]);
                MMA16816(sacc[2 * np],     qhf[ks], &bl[0]);
                MMA16816(sacc[2 * np],     al,      &bh[0]);
                MMA16816(sacc[2 * np + 1], qhf[ks], &bh[2]);
                MMA16816(sacc[2 * np + 1], qhf[ks], &bl[2]);
                MMA16816(sacc[2 * np + 1], al,      &bh[2]);
            }
        }

        const int j0 = blk * 64;
        if (j0 + 63 > q0 + WIN) {
            const int rq = q0 + r0 + (lane >> 2);
#pragma unroll
            for (int nf = 0; nf < 8; nf++) {
#pragma unroll
                for (int e = 0; e < 2; e++) {
                    int k = j0 + nf * 8 + (lane & 3) * 2 + e;
                    if (k > rq + WIN)     sacc[nf][e]     = -1e30f;
                    if (k > rq + 8 + WIN) sacc[nf][2 + e] = -1e30f;
                }
            }
        }

        float mx0 = -1e30f, mx1 = -1e30f;
#pragma unroll
        for (int nf = 0; nf < 8; nf++) {
            mx0 = fmaxf(mx0, fmaxf(sacc[nf][0], sacc[nf][1]));
            mx1 = fmaxf(mx1, fmaxf(sacc[nf][2], sacc[nf][3]));
        }
        mx0 = fmaxf(mx0, __shfl_xor_sync(0xffffffffu, mx0, 1));
        mx0 = fmaxf(mx0, __shfl_xor_sync(0xffffffffu, mx0, 2));
        mx1 = fmaxf(mx1, __shfl_xor_sync(0xffffffffu, mx1, 1));
        mx1 = fmaxf(mx1, __shfl_xor_sync(0xffffffffu, mx1, 2));
        float mn0 = fmaxf(m0r, mx0), mn1 = fmaxf(m1r, mx1);
        float a0 = ex2(m0r - mn0), a1 = ex2(m1r - mn1);
        m0r = mn0; m1r = mn1;
        float s0 = 0.f, s1 = 0.f;
#pragma unroll
        for (int nf = 0; nf < 8; nf++) {
            sacc[nf][0] = ex2(sacc[nf][0] - mn0);
            sacc[nf][1] = ex2(sacc[nf][1] - mn0);
            sacc[nf][2] = ex2(sacc[nf][2] - mn1);
            sacc[nf][3] = ex2(sacc[nf][3] - mn1);
            s0 += sacc[nf][0] + sacc[nf][1];
            s1 += sacc[nf][2] + sacc[nf][3];
        }
        s0 += __shfl_xor_sync(0xffffffffu, s0, 1);
        s0 += __shfl_xor_sync(0xffffffffu, s0, 2);
        s1 += __shfl_xor_sync(0xffffffffu, s1, 1);
        s1 += __shfl_xor_sync(0xffffffffu, s1, 2);
        l0r = l0r * a0 + s0;
        l1r = l1r * a1 + s1;
#pragma unroll
        for (int df = 0; df < 16; df++) {
            oacc[df][0] *= a0; oacc[df][1] *= a0;
            oacc[df][2] *= a1; oacc[df][3] *= a1;
        }

        // O += P V  (full 3-product: PhVh + PhVl + PlVh — R9 showed P-lo is required)
#pragma unroll
        for (int kk = 0; kk < 4; kk++) {
            const float* f0 = sacc[2 * kk];
            const float* f1 = sacc[2 * kk + 1];
            uint32_t ph[4], pl[4];
            ph[0] = bf2(f0[0], f0[1]); ph[1] = bf2(f0[2], f0[3]);
            ph[2] = bf2(f1[0], f1[1]); ph[3] = bf2(f1[2], f1[3]);
            pl[0] = bf2(bfres(f0[0]), bfres(f0[1]));
            pl[1] = bf2(bfres(f0[2]), bfres(f0[3]));
            pl[2] = bf2(bfres(f1[0]), bfres(f1[1]));
            pl[3] = bf2(bfres(f1[2]), bfres(f1[3]));
#pragma unroll
            for (int dp = 0; dp < 8; dp++) {
                uint32_t bvh[4], bvl[4];
                uint32_t va = vb + (uint32_t)((kk * 16 + (lane & 15)) * AP +
                                              dp * 16 + ((lane >> 4) << 3)) * 2;
                LDM_X4_T(bvh, va);
                LDM_X4_T(bvl, va + KVT * 2);
                MMA16816(oacc[2 * dp],     ph, &bvh[0]);
                MMA16816(oacc[2 * dp],     ph, &bvl[0]);
                MMA16816(oacc[2 * dp],     pl, &bvh[0]);
                MMA16816(oacc[2 * dp + 1], ph, &bvh[2]);
                MMA16816(oacc[2 * dp + 1], ph, &bvl[2]);
                MMA16816(oacc[2 * dp + 1], pl, &bvh[2]);
            }
        }
        __syncthreads();
    }

    const float inv0 = 1.0f / l0r;
    const float inv1 = 1.0f / l1r;
    const int rq = q0 + r0 + (lane >> 2);
    size_t base0 = (((size_t)b * SS + rq) * HH + h) * DHD;
    size_t base1 = base0 + (size_t)8 * HH * DHD;
#pragma unroll
    for (int df = 0; df < 16; df++) {
        int col = df * 8 + (lane & 3) * 2;
        float v0 = oacc[df][0] * inv0, v1 = oacc[df][1] * inv0;
        float v2 = oacc[df][2] * inv1, v3 = oacc[df][3] * inv1;
        __nv_bfloat16 h0 = __float2bfloat16(v0), h1 = __float2bfloat16(v1);
        __nv_bfloat16 h2 = __float2bfloat16(v2), h3 = __float2bfloat16(v3);
        *(__nv_bfloat162*)(Ohi + base0 + col) = __nv_bfloat162(h0, h1);
        *(__nv_bfloat162*)(Ohi + base1 + col) = __nv_bfloat162(h2, h3);
        *(__nv_bfloat162*)(Olo + base0 + col) = __nv_bfloat162(
            __float2bfloat16(v0 - __bfloat162float(h0)),
            __float2bfloat16(v1 - __bfloat162float(h1)));
        *(__nv_bfloat162*)(Olo + base1 + col) = __nv_bfloat162(
            __float2bfloat16(v2 - __bfloat162float(h2)),
            __float2bfloat16(v3 - __bfloat162float(h3)));
    }
}

// ---------------- launch ----------------------------------------------------
extern "C" void kernel_launch(void* const* d_in, const int* in_sizes, int n_in,
                              void* d_out, int out_size) {
    const float* x  = (const float*)d_in[0];
    const float* Wq = (const float*)d_in[1];
    const float* Wk = (const float*)d_in[2];
    const float* Wv = (const float*)d_in[3];
    const float* Wo = (const float*)d_in[4];
    float* out = (float*)d_out;

    void *pxh, *pxl, *pqh, *pql, *pkh, *pkl, *pvh, *pvl, *poh, *pol, *pah, *pal;
    void *aqh, *aql, *akh, *akl, *avh, *avl;
    cudaGetSymbolAddress(&pxh, g_xhi);  cudaGetSymbolAddress(&pxl, g_xlo);
    cudaGetSymbolAddress(&pqh, g_wqhi); cudaGetSymbolAddress(&pql, g_wqlo);
    cudaGetSymbolAddress(&pkh, g_wkhi); cudaGetSymbolAddress(&pkl, g_wklo);
    cudaGetSymbolAddress(&pvh, g_wvhi); cudaGetSymbolAddress(&pvl, g_wvlo);
    cudaGetSymbolAddress(&poh, g_wohi); cudaGetSymbolAddress(&pol, g_wolo);
    cudaGetSymbolAddress(&pah, g_ahi);  cudaGetSymbolAddress(&pal, g_alo);
    cudaGetSymbolAddress(&aqh, g_qah);  cudaGetSymbolAddress(&aql, g_qal);
    cudaGetSymbolAddress(&akh, g_kah);  cudaGetSymbolAddress(&akl, g_kal);
    cudaGetSymbolAddress(&avh, g_vah);  cudaGetSymbolAddress(&avl, g_val);

    cudaFuncSetAttribute(gemm_qkv,
                         cudaFuncAttributeMaxDynamicSharedMemorySize, GEMM_SMEM_B);
    cudaFuncSetAttribute(gemm_mma,
                         cudaFuncAttributeMaxDynamicSharedMemorySize, GEMM_SMEM_B);
    cudaFuncSetAttribute(attn_mma,
                         cudaFuncAttributeMaxDynamicSharedMemorySize, ATT_SMEM_B);

    // 1. RoPE tables
    rope_tables_kernel<<<(SS * 64 + 255) / 256, 256>>>();

    // 2. All hi/lo splits in one launch
    split_all_kernel<<<X4B + WQ4B + WK4B + WV4B + WO4B, 256>>>(
        x,  (__nv_bfloat16*)pxh, (__nv_bfloat16*)pxl,
        Wq, (__nv_bfloat16*)pqh, (__nv_bfloat16*)pql,
        Wk, (__nv_bfloat16*)pkh, (__nv_bfloat16*)pkl,
        Wv, (__nv_bfloat16*)pvh, (__nv_bfloat16*)pvl,
        Wo, (__nv_bfloat16*)poh, (__nv_bfloat16*)pol);

    // 3. Fused Q/K/V projections with RoPE+split epilogue
    gemm_qkv<<<dim3(24, MTOK / 128), 256, GEMM_SMEM_B>>>(
        (const __nv_bfloat16*)pxh, (const __nv_bfloat16*)pxl,
        (const __nv_bfloat16*)pqh, (const __nv_bfloat16*)pql,
        (const __nv_bfloat16*)pkh, (const __nv_bfloat16*)pkl,
        (const __nv_bfloat16*)pvh, (const __nv_bfloat16*)pvl,
        (__nv_bfloat16*)aqh, (__nv_bfloat16*)aql,
        (__nv_bfloat16*)akh, (__nv_bfloat16*)akl,
        (__nv_bfloat16*)avh, (__nv_bfloat16*)avl);

    // 4. Attention -> bf16 hi/lo
    attn_mma<<<dim3(SS / 128, HH, BB), 256, ATT_SMEM_B>>>(
        (const __nv_bfloat16*)aqh, (const __nv_bfloat16*)aql,
        (const __nv_bfloat16*)akh, (const __nv_bfloat16*)akl,
        (const __nv_bfloat16*)avh, (const __nv_bfloat16*)avl,
        (__nv_bfloat16*)pah, (__nv_bfloat16*)pal);

    // 5. O projection
    gemm_mma<<<dim3(DD / 128, MTOK / 128), 256, GEMM_SMEM_B>>>(
        (const __nv_bfloat16*)pah, (const __nv_bfloat16*)pal,
        (const __nv_bfloat16*)poh, (const __nv_bfloat16*)pol,
        out, MTOK, DD, NQ);
}